// round 1
// baseline (speedup 1.0000x reference)
#include <cuda_runtime.h>
#include <math.h>
#include <math_constants.h>

// Problem constants
#define Bb   16
#define Kk   16
#define Ss   512
#define Ee   512
#define Ll   16
#define Hh   8
#define KVHn 2
#define Dd   64
#define BINn 50
#define HD   (Hh*Dd)        // 512
#define KVHD (KVHn*Dd)      // 128
#define NKV  (2*KVHD)       // 256 (K cols 0..127, V cols 128..255)
#define BKTOT (Bb*Kk)       // 256
#define MROWS (BKTOT*Ss)    // 131072

// Scratch (static device globals; no runtime allocation)
__device__ float g_xkv[(size_t)MROWS * NKV];     // 128 MiB: [bk*S+s][n] n<128:xk raw, n>=128:xv
__device__ float g_xq[Ll * HD];                  // scaled queries (L, H*D)
__device__ float g_att[(size_t)BKTOT * Ll * HD]; // 8 MiB: [bk][l][h][d]

// ---------------------------------------------------------------------------
// K1: xq = (latent_query @ Wq^T) * (1/sqrt(D)).  Tiny.
// grid: L blocks, 512 threads (one output column each)
// ---------------------------------------------------------------------------
__global__ void xq_kernel(const float* __restrict__ lq, const float* __restrict__ Wq)
{
    int l = blockIdx.x;
    __shared__ float qs[Ee];
    for (int e = threadIdx.x; e < Ee; e += blockDim.x) qs[e] = lq[l * Ee + e];
    __syncthreads();
    int j = threadIdx.x;                    // 0..511 == h*D+d
    const float* w = Wq + (size_t)j * Ee;
    float acc = 0.f;
#pragma unroll 8
    for (int e = 0; e < Ee; e++) acc += qs[e] * __ldg(&w[e]);
    g_xq[l * HD + j] = acc * 0.125f;        // 1/sqrt(64)
}

// ---------------------------------------------------------------------------
// Generic NT SGEMM: C[m][n] = sum_k A[m][k] * B[n][k]
// B row n comes from B0 (n < nsplit) or B1 (row n-nsplit) -> lets us fuse Wk|Wv.
// Tiles: BM=128, BN=128, BK=16, 256 threads, 8x8 per thread.
// Requires: M % 128 == 0, N % 128 == 0, Kd % 16 == 0, 16B-aligned pointers.
// ---------------------------------------------------------------------------
__global__ __launch_bounds__(256) void gemm_nt(
    const float* __restrict__ A,
    const float* __restrict__ B0,
    const float* __restrict__ B1,
    int nsplit,
    float* __restrict__ C,
    int N, int Kd)
{
    const int BM = 128, BN = 128, BK = 16;
    __shared__ float As[BK][BM];
    __shared__ float Bs[BK][BN];

    int m0 = blockIdx.y * BM;
    int n0 = blockIdx.x * BN;
    int tid = threadIdx.x;
    int tx = tid & 15;          // 0..15 (n direction)
    int ty = tid >> 4;          // 0..15 (m direction)

    float acc[8][8];
#pragma unroll
    for (int i = 0; i < 8; i++)
#pragma unroll
        for (int j = 0; j < 8; j++) acc[i][j] = 0.f;

    int ldRow = tid >> 2;       // 0..63
    int ldCol = (tid & 3) * 4;  // 0,4,8,12

    for (int k0 = 0; k0 < Kd; k0 += BK) {
        // A tile (BM x BK), stored transposed As[k][m]
#pragma unroll
        for (int p = 0; p < 2; p++) {
            int r = ldRow + p * 64;
            float4 v = *reinterpret_cast<const float4*>(
                A + (size_t)(m0 + r) * Kd + k0 + ldCol);
            As[ldCol + 0][r] = v.x; As[ldCol + 1][r] = v.y;
            As[ldCol + 2][r] = v.z; As[ldCol + 3][r] = v.w;
        }
        // B tile (BN x BK), stored transposed Bs[k][n]
#pragma unroll
        for (int p = 0; p < 2; p++) {
            int r = ldRow + p * 64;
            int n = n0 + r;
            const float* Bp = (n < nsplit) ? (B0 + (size_t)n * Kd)
                                           : (B1 + (size_t)(n - nsplit) * Kd);
            float4 v = *reinterpret_cast<const float4*>(Bp + k0 + ldCol);
            Bs[ldCol + 0][r] = v.x; Bs[ldCol + 1][r] = v.y;
            Bs[ldCol + 2][r] = v.z; Bs[ldCol + 3][r] = v.w;
        }
        __syncthreads();

#pragma unroll
        for (int kk = 0; kk < BK; kk++) {
            float a[8], b[8];
            float4 a0 = *reinterpret_cast<const float4*>(&As[kk][ty * 8]);
            float4 a1 = *reinterpret_cast<const float4*>(&As[kk][ty * 8 + 4]);
            float4 b0 = *reinterpret_cast<const float4*>(&Bs[kk][tx * 8]);
            float4 b1 = *reinterpret_cast<const float4*>(&Bs[kk][tx * 8 + 4]);
            a[0]=a0.x; a[1]=a0.y; a[2]=a0.z; a[3]=a0.w;
            a[4]=a1.x; a[5]=a1.y; a[6]=a1.z; a[7]=a1.w;
            b[0]=b0.x; b[1]=b0.y; b[2]=b0.z; b[3]=b0.w;
            b[4]=b1.x; b[5]=b1.y; b[6]=b1.z; b[7]=b1.w;
#pragma unroll
            for (int i = 0; i < 8; i++)
#pragma unroll
                for (int j = 0; j < 8; j++)
                    acc[i][j] += a[i] * b[j];
        }
        __syncthreads();
    }

#pragma unroll
    for (int i = 0; i < 8; i++) {
        int row = m0 + ty * 8 + i;
        float4 c0 = make_float4(acc[i][0], acc[i][1], acc[i][2], acc[i][3]);
        float4 c1 = make_float4(acc[i][4], acc[i][5], acc[i][6], acc[i][7]);
        float* cp = C + (size_t)row * N + n0 + tx * 8;
        *reinterpret_cast<float4*>(cp)     = c0;
        *reinterpret_cast<float4*>(cp + 4) = c1;
    }
}

// ---------------------------------------------------------------------------
// K3: attention per (bk, h). RoPE on K applied at load (cos/sin halves are
// duplicated: table[d+32] == table[d] for d<32). Ragged mask via spike_lengths.
// grid: (H, B*K), 128 threads.
// ---------------------------------------------------------------------------
__global__ __launch_bounds__(128) void attn_kernel(
    const int* __restrict__ offsets,
    const int* __restrict__ slen,
    const float* __restrict__ cosT,
    const float* __restrict__ sinT)
{
    int h   = blockIdx.x;
    int bk  = blockIdx.y;
    int kvh = h >> 2;               // n_rep = 4 (repeat-interleave)
    int tid = threadIdx.x;

    __shared__ float qsh[Ll][Dd];   // 4 KB
    __shared__ float sc[Ll][Ss];    // 32 KB

    for (int i = tid; i < Ll * Dd; i += 128) {
        int l = i >> 6, d = i & 63;
        qsh[l][d] = g_xq[l * HD + h * Dd + d];
    }
    __syncthreads();

    int len = slen[bk];

    // Phase 1: scores[l][s] = q_l . RoPE(k_s)
    for (int it = 0; it < 4; it++) {
        int s = tid + it * 128;
        const float* kp = &g_xkv[((size_t)(bk * Ss + s)) * NKV + kvh * Dd];
        float kt[Dd];
#pragma unroll
        for (int d4 = 0; d4 < Dd; d4 += 4) {
            float4 v = *reinterpret_cast<const float4*>(kp + d4);
            kt[d4] = v.x; kt[d4+1] = v.y; kt[d4+2] = v.z; kt[d4+3] = v.w;
        }
        int o = offsets[bk * Ss + s];
        const float* cp = cosT + o * Dd;
        const float* sp = sinT + o * Dd;
#pragma unroll
        for (int d = 0; d < 32; d++) {
            float c  = __ldg(&cp[d]);
            float si = __ldg(&sp[d]);
            float lo = kt[d], hi = kt[d + 32];
            kt[d]      = lo * c - hi * si;
            kt[d + 32] = hi * c + lo * si;
        }
        bool valid = (s < len);
        for (int l = 0; l < Ll; l++) {
            float acc = 0.f;
#pragma unroll
            for (int d = 0; d < Dd; d++) acc += qsh[l][d] * kt[d];
            sc[l][s] = valid ? acc : -CUDART_INF_F;
        }
    }
    __syncthreads();

    // Phase 2: softmax over s, one warp per 4 rows
    int w = tid >> 5, lane = tid & 31;
    for (int l = w; l < Ll; l += 4) {
        float mx = -CUDART_INF_F;
        for (int i = lane; i < Ss; i += 32) mx = fmaxf(mx, sc[l][i]);
#pragma unroll
        for (int off = 16; off; off >>= 1)
            mx = fmaxf(mx, __shfl_xor_sync(0xffffffffu, mx, off));
        float sum = 0.f;
        for (int i = lane; i < Ss; i += 32) {
            float e = __expf(sc[l][i] - mx);
            sc[l][i] = e;
            sum += e;
        }
#pragma unroll
        for (int off = 16; off; off >>= 1)
            sum += __shfl_xor_sync(0xffffffffu, sum, off);
        float inv = 1.f / sum;
        for (int i = lane; i < Ss; i += 32) sc[l][i] *= inv;
    }
    __syncthreads();

    // Phase 3: out[l][d] = sum_s attn[l][s] * v[s][d]
    int l  = tid >> 3;
    int dg = (tid & 7) * 8;
    float acc[8];
#pragma unroll
    for (int j = 0; j < 8; j++) acc[j] = 0.f;
    const float* vbase = &g_xkv[((size_t)bk * Ss) * NKV + KVHD + kvh * Dd + dg];
    for (int s = 0; s < Ss; s++) {
        float a = sc[l][s];
        const float* vp = vbase + (size_t)s * NKV;
        float4 v0 = *reinterpret_cast<const float4*>(vp);
        float4 v1 = *reinterpret_cast<const float4*>(vp + 4);
        acc[0] += a * v0.x; acc[1] += a * v0.y;
        acc[2] += a * v0.z; acc[3] += a * v0.w;
        acc[4] += a * v1.x; acc[5] += a * v1.y;
        acc[6] += a * v1.z; acc[7] += a * v1.w;
    }
    float* op = &g_att[(((size_t)bk * Ll + l) * Hh + h) * Dd + dg];
    *reinterpret_cast<float4*>(op)     = make_float4(acc[0], acc[1], acc[2], acc[3]);
    *reinterpret_cast<float4*>(op + 4) = make_float4(acc[4], acc[5], acc[6], acc[7]);
}

// ---------------------------------------------------------------------------
extern "C" void kernel_launch(void* const* d_in, const int* in_sizes, int n_in,
                              void* d_out, int out_size)
{
    const float* spike  = (const float*)d_in[0];
    const int*   offs   = (const int*)  d_in[1];
    const int*   slen   = (const int*)  d_in[2];
    const float* cosT   = (const float*)d_in[3];
    const float* sinT   = (const float*)d_in[4];
    const float* lq     = (const float*)d_in[5];
    const float* Wq     = (const float*)d_in[6];
    const float* Wk     = (const float*)d_in[7];
    const float* Wv     = (const float*)d_in[8];
    const float* Wo     = (const float*)d_in[9];
    float* out = (float*)d_out;

    void* xkv_p = nullptr;
    void* att_p = nullptr;
    cudaGetSymbolAddress(&xkv_p, g_xkv);
    cudaGetSymbolAddress(&att_p, g_att);

    // K1: queries (tiny)
    xq_kernel<<<Ll, Ee>>>(lq, Wq);

    // K2: fused K|V projection: (131072 x 512) @ (512 x 256)^T
    gemm_nt<<<dim3(NKV / 128, MROWS / 128), 256>>>(
        spike, Wk, Wv, KVHD, (float*)xkv_p, NKV, Ee);

    // K3: attention (RoPE + scores + softmax + AV)
    attn_kernel<<<dim3(Hh, BKTOT), 128>>>(offs, slen, cosT, sinT);

    // K4: output projection: (4096 x 512) @ (512 x 512)^T
    gemm_nt<<<dim3(Ee / 128, (BKTOT * Ll) / 128), 256>>>(
        (const float*)att_p, Wo, Wo, 1 << 30, out, Ee, HD);
}

// round 3
// speedup vs baseline: 1.0306x; 1.0306x over previous
#include <cuda_runtime.h>
#include <math.h>
#include <math_constants.h>
#include <stdint.h>

// Problem constants
#define Bb   16
#define Kk   16
#define Ss   512
#define Ee   512
#define Ll   16
#define Hh   8
#define KVHn 2
#define Dd   64
#define HD   (Hh*Dd)        // 512
#define KVHD (KVHn*Dd)      // 128
#define NKV  (2*KVHD)       // 256
#define BKTOT (Bb*Kk)       // 256
#define MROWS (BKTOT*Ss)    // 131072

// Scratch (static device globals)
__device__ float g_xkv[(size_t)MROWS * NKV];     // [bk*S+s][n] n<128:xk, n>=128:xv
__device__ float g_xq[Ll * HD];
__device__ float g_att[(size_t)BKTOT * Ll * HD]; // [bk][l][h][d]

// ---------------------------------------------------------------------------
// Helpers: cp.async + tf32 mma.sync (sm_80+ features, compile on base sm_103)
// ---------------------------------------------------------------------------
__device__ __forceinline__ void cp_async16(uint32_t saddr, const float* gptr) {
    asm volatile("cp.async.cg.shared.global [%0], [%1], 16;"
                 :: "r"(saddr), "l"(gptr) : "memory");
}
#define CP_COMMIT() asm volatile("cp.async.commit_group;" ::: "memory")
#define CP_WAIT(n)  asm volatile("cp.async.wait_group %0;" :: "n"(n) : "memory")

__device__ __forceinline__ uint32_t f2tf32(float f) {
    uint32_t r;
    asm("cvt.rna.tf32.f32 %0, %1;" : "=r"(r) : "f"(f));
    return r;
}

__device__ __forceinline__ void mma_tf32(float* c, const uint32_t* a, const uint32_t* b) {
    asm volatile(
        "mma.sync.aligned.m16n8k8.row.col.f32.tf32.tf32.f32 "
        "{%0,%1,%2,%3}, {%4,%5,%6,%7}, {%8,%9}, {%0,%1,%2,%3};"
        : "+f"(c[0]), "+f"(c[1]), "+f"(c[2]), "+f"(c[3])
        : "r"(a[0]), "r"(a[1]), "r"(a[2]), "r"(a[3]), "r"(b[0]), "r"(b[1]));
}

// ---------------------------------------------------------------------------
// tf32 NT GEMM: C[m][n] = sum_k A[m][k] * B[n][k]
// B row n from B0 (n<nsplit) or B1 (row n-nsplit) -> fuses Wk|Wv.
// CTA tile 128x128, BK=16, 256 threads, 8 warps each with a 32x64 warp tile.
// Requires M%128==0, N%128==0, Kd%16==0.
// ---------------------------------------------------------------------------
#define PADW 20          // padded row stride in floats (conflict-free frag reads)

__global__ void __launch_bounds__(256, 2) gemm_mma(
    const float* __restrict__ A,
    const float* __restrict__ B0,
    const float* __restrict__ B1,
    int nsplit,
    float* __restrict__ C,
    int N, int Kd)
{
    __shared__ float As[2][128 * PADW];
    __shared__ float Bs[2][128 * PADW];

    int tid  = threadIdx.x;
    int wid  = tid >> 5, lane = tid & 31;
    int m0   = blockIdx.y * 128;
    int n0   = blockIdx.x * 128;
    int wm   = (wid & 3) * 32;     // warp m-offset within tile
    int wn   = (wid >> 2) * 64;    // warp n-offset within tile

    float acc[2][8][4];
#pragma unroll
    for (int mt = 0; mt < 2; mt++)
#pragma unroll
        for (int nt = 0; nt < 8; nt++)
#pragma unroll
            for (int j = 0; j < 4; j++) acc[mt][nt][j] = 0.f;

    // loader mapping: each thread copies one 16B chunk in rows [0,64) and [64,128)
    int ldrow = tid >> 2;          // 0..63
    int ldc   = (tid & 3) * 4;     // float col offset 0,4,8,12

    const float* ag0 = A + (size_t)(m0 + ldrow)      * Kd + ldc;
    const float* ag1 = A + (size_t)(m0 + ldrow + 64) * Kd + ldc;
    int nr0 = n0 + ldrow, nr1 = n0 + ldrow + 64;
    const float* bg0 = ((nr0 < nsplit) ? B0 + (size_t)nr0 * Kd
                                       : B1 + (size_t)(nr0 - nsplit) * Kd) + ldc;
    const float* bg1 = ((nr1 < nsplit) ? B0 + (size_t)nr1 * Kd
                                       : B1 + (size_t)(nr1 - nsplit) * Kd) + ldc;

    uint32_t sa_base = (uint32_t)__cvta_generic_to_shared(&As[0][0]);
    uint32_t sb_base = (uint32_t)__cvta_generic_to_shared(&Bs[0][0]);
    uint32_t stg_sz  = 128 * PADW * 4;
    uint32_t dA0 = sa_base + ((uint32_t)ldrow * PADW + ldc) * 4;
    uint32_t dA1 = sa_base + ((uint32_t)(ldrow + 64) * PADW + ldc) * 4;
    uint32_t dB0 = sb_base + ((uint32_t)ldrow * PADW + ldc) * 4;
    uint32_t dB1 = sb_base + ((uint32_t)(ldrow + 64) * PADW + ldc) * 4;

    int NIT = Kd >> 4;

    // prologue: stage 0
    cp_async16(dA0, ag0); cp_async16(dA1, ag1);
    cp_async16(dB0, bg0); cp_async16(dB1, bg1);
    CP_COMMIT();

    for (int it = 0; it < NIT; it++) {
        int cur = it & 1;
        if (it + 1 < NIT) {
            int nk  = (it + 1) << 4;
            uint32_t so = (uint32_t)((it + 1) & 1) * stg_sz;
            cp_async16(dA0 + so, ag0 + nk); cp_async16(dA1 + so, ag1 + nk);
            cp_async16(dB0 + so, bg0 + nk); cp_async16(dB1 + so, bg1 + nk);
            CP_COMMIT();
            CP_WAIT(1);
        } else {
            CP_WAIT(0);
        }
        __syncthreads();

        const float* as = As[cur];
        const float* bs = Bs[cur];
#pragma unroll
        for (int ks = 0; ks < 2; ks++) {
            int k0 = ks * 8 + (lane & 3);
            uint32_t af[2][4], bf[8][2];
#pragma unroll
            for (int mt = 0; mt < 2; mt++) {
                int r = wm + mt * 16 + (lane >> 2);
                af[mt][0] = f2tf32(as[r * PADW + k0]);
                af[mt][1] = f2tf32(as[(r + 8) * PADW + k0]);
                af[mt][2] = f2tf32(as[r * PADW + k0 + 4]);
                af[mt][3] = f2tf32(as[(r + 8) * PADW + k0 + 4]);
            }
#pragma unroll
            for (int nt = 0; nt < 8; nt++) {
                int n = wn + nt * 8 + (lane >> 2);
                bf[nt][0] = f2tf32(bs[n * PADW + k0]);
                bf[nt][1] = f2tf32(bs[n * PADW + k0 + 4]);
            }
#pragma unroll
            for (int mt = 0; mt < 2; mt++)
#pragma unroll
                for (int nt = 0; nt < 8; nt++)
                    mma_tf32(acc[mt][nt], af[mt], bf[nt]);
        }
        __syncthreads();
    }

    // epilogue: direct float2 stores
#pragma unroll
    for (int mt = 0; mt < 2; mt++) {
        int row = m0 + wm + mt * 16 + (lane >> 2);
#pragma unroll
        for (int nt = 0; nt < 8; nt++) {
            int col = n0 + wn + nt * 8 + (lane & 3) * 2;
            *reinterpret_cast<float2*>(C + (size_t)row * N + col) =
                make_float2(acc[mt][nt][0], acc[mt][nt][1]);
            *reinterpret_cast<float2*>(C + (size_t)(row + 8) * N + col) =
                make_float2(acc[mt][nt][2], acc[mt][nt][3]);
        }
    }
}

// ---------------------------------------------------------------------------
// K1: xq = (latent_query @ Wq^T) / sqrt(D)
// ---------------------------------------------------------------------------
__global__ void xq_kernel(const float* __restrict__ lq, const float* __restrict__ Wq)
{
    int l = blockIdx.x;
    __shared__ float qs[Ee];
    for (int e = threadIdx.x; e < Ee; e += blockDim.x) qs[e] = lq[l * Ee + e];
    __syncthreads();
    int j = threadIdx.x;
    const float* w = Wq + (size_t)j * Ee;
    float acc = 0.f;
#pragma unroll 8
    for (int e = 0; e < Ee; e++) acc += qs[e] * __ldg(&w[e]);
    g_xq[l * HD + j] = acc * 0.125f;
}

// ---------------------------------------------------------------------------
// K3: attention per (bk, h): RoPE(K) + scores + ragged softmax + AV (fp32)
// ---------------------------------------------------------------------------
__global__ void __launch_bounds__(128) attn_kernel(
    const int* __restrict__ offsets,
    const int* __restrict__ slen,
    const float* __restrict__ cosT,
    const float* __restrict__ sinT)
{
    int h   = blockIdx.x;
    int bk  = blockIdx.y;
    int kvh = h >> 2;
    int tid = threadIdx.x;

    __shared__ float qsh[Ll][Dd];
    __shared__ float sc[Ll][Ss];

    for (int i = tid; i < Ll * Dd; i += 128) {
        int l = i >> 6, d = i & 63;
        qsh[l][d] = g_xq[l * HD + h * Dd + d];
    }
    __syncthreads();

    int len = slen[bk];

    for (int it = 0; it < 4; it++) {
        int s = tid + it * 128;
        const float* kp = &g_xkv[((size_t)(bk * Ss + s)) * NKV + kvh * Dd];
        float kt[Dd];
#pragma unroll
        for (int d4 = 0; d4 < Dd; d4 += 4) {
            float4 v = *reinterpret_cast<const float4*>(kp + d4);
            kt[d4] = v.x; kt[d4+1] = v.y; kt[d4+2] = v.z; kt[d4+3] = v.w;
        }
        int o = offsets[bk * Ss + s];
        const float* cp = cosT + o * Dd;
        const float* sp = sinT + o * Dd;
#pragma unroll
        for (int d = 0; d < 32; d++) {
            float c  = __ldg(&cp[d]);
            float si = __ldg(&sp[d]);
            float lo = kt[d], hi = kt[d + 32];
            kt[d]      = lo * c - hi * si;
            kt[d + 32] = hi * c + lo * si;
        }
        bool valid = (s < len);
        for (int l = 0; l < Ll; l++) {
            float acc = 0.f;
#pragma unroll
            for (int d = 0; d < Dd; d++) acc += qsh[l][d] * kt[d];
            sc[l][s] = valid ? acc : -CUDART_INF_F;
        }
    }
    __syncthreads();

    int w = tid >> 5, lane = tid & 31;
    for (int l = w; l < Ll; l += 4) {
        float mx = -CUDART_INF_F;
        for (int i = lane; i < Ss; i += 32) mx = fmaxf(mx, sc[l][i]);
#pragma unroll
        for (int off = 16; off; off >>= 1)
            mx = fmaxf(mx, __shfl_xor_sync(0xffffffffu, mx, off));
        float sum = 0.f;
        for (int i = lane; i < Ss; i += 32) {
            float e = __expf(sc[l][i] - mx);
            sc[l][i] = e;
            sum += e;
        }
#pragma unroll
        for (int off = 16; off; off >>= 1)
            sum += __shfl_xor_sync(0xffffffffu, sum, off);
        float inv = 1.f / sum;
        for (int i = lane; i < Ss; i += 32) sc[l][i] *= inv;
    }
    __syncthreads();

    int l  = tid >> 3;
    int dg = (tid & 7) * 8;
    float acc[8];
#pragma unroll
    for (int j = 0; j < 8; j++) acc[j] = 0.f;
    const float* vbase = &g_xkv[((size_t)bk * Ss) * NKV + KVHD + kvh * Dd + dg];
    for (int s = 0; s < Ss; s++) {
        float a = sc[l][s];
        const float* vp = vbase + (size_t)s * NKV;
        float4 v0 = *reinterpret_cast<const float4*>(vp);
        float4 v1 = *reinterpret_cast<const float4*>(vp + 4);
        acc[0] += a * v0.x; acc[1] += a * v0.y;
        acc[2] += a * v0.z; acc[3] += a * v0.w;
        acc[4] += a * v1.x; acc[5] += a * v1.y;
        acc[6] += a * v1.z; acc[7] += a * v1.w;
    }
    float* op = &g_att[(((size_t)bk * Ll + l) * Hh + h) * Dd + dg];
    *reinterpret_cast<float4*>(op)     = make_float4(acc[0], acc[1], acc[2], acc[3]);
    *reinterpret_cast<float4*>(op + 4) = make_float4(acc[4], acc[5], acc[6], acc[7]);
}

// ---------------------------------------------------------------------------
extern "C" void kernel_launch(void* const* d_in, const int* in_sizes, int n_in,
                              void* d_out, int out_size)
{
    const float* spike  = (const float*)d_in[0];
    const int*   offs   = (const int*)  d_in[1];
    const int*   slen   = (const int*)  d_in[2];
    const float* cosT   = (const float*)d_in[3];
    const float* sinT   = (const float*)d_in[4];
    const float* lq     = (const float*)d_in[5];
    const float* Wq     = (const float*)d_in[6];
    const float* Wk     = (const float*)d_in[7];
    const float* Wv     = (const float*)d_in[8];
    const float* Wo     = (const float*)d_in[9];
    float* out = (float*)d_out;

    void* xkv_p = nullptr;
    void* att_p = nullptr;
    cudaGetSymbolAddress(&xkv_p, g_xkv);
    cudaGetSymbolAddress(&att_p, g_att);

    // K1: queries (tiny)
    xq_kernel<<<Ll, Ee>>>(lq, Wq);

    // K2: fused K|V projection (131072 x 256 x 512), tf32 mma.sync
    gemm_mma<<<dim3(NKV / 128, MROWS / 128), 256>>>(
        spike, Wk, Wv, KVHD, (float*)xkv_p, NKV, Ee);

    // K3: attention (RoPE + scores + softmax + AV)
    attn_kernel<<<dim3(Hh, BKTOT), 128>>>(offs, slen, cosT, sinT);

    // K4: output projection (4096 x 512 x 512), tf32 mma.sync
    gemm_mma<<<dim3(Ee / 128, (BKTOT * Ll) / 128), 256>>>(
        (const float*)att_p, Wo, Wo, 1 << 30, out, Ee, HD);
}

// round 5
// speedup vs baseline: 2.6726x; 2.5932x over previous
#include <cuda_runtime.h>
#include <cuda_fp16.h>
#include <math.h>
#include <math_constants.h>
#include <stdint.h>

// Problem constants
#define Bb   16
#define Kk   16
#define Ss   512
#define Ee   512
#define Ll   16
#define Hh   8
#define KVHn 2
#define Dd   64
#define HD   (Hh*Dd)        // 512
#define KVHD (KVHn*Dd)      // 128
#define NKV  (2*KVHD)       // 256
#define BKTOT (Bb*Kk)       // 256
#define MROWS (BKTOT*Ss)    // 131072

// Scratch (static device globals)
__device__ __half g_spike_h[(size_t)MROWS * Ee];   // fp16 spike
__device__ __half g_wkv_h[NKV * Ee];               // [Wk;Wv] fp16
__device__ __half g_xkv_h[(size_t)MROWS * NKV];    // K(rope'd)|V fp16
__device__ float  g_xq[Ll * HD];                   // scaled queries fp32
__device__ float  g_att[(size_t)BKTOT * Ll * HD];  // attention out fp32

// ---------------------------------------------------------------------------
// PTX helpers
// ---------------------------------------------------------------------------
__device__ __forceinline__ void cp_async16(uint32_t saddr, const void* gptr) {
    asm volatile("cp.async.cg.shared.global [%0], [%1], 16;"
                 :: "r"(saddr), "l"(gptr) : "memory");
}
#define CP_COMMIT() asm volatile("cp.async.commit_group;" ::: "memory")
#define CP_WAIT(n)  asm volatile("cp.async.wait_group %0;" :: "n"(n) : "memory")

__device__ __forceinline__ uint32_t lds32(uint32_t addr) {
    uint32_t v;
    asm volatile("ld.shared.b32 %0, [%1];" : "=r"(v) : "r"(addr));
    return v;
}

__device__ __forceinline__ uint32_t f2tf32(float f) {
    uint32_t r;
    asm("cvt.rna.tf32.f32 %0, %1;" : "=r"(r) : "f"(f));
    return r;
}

__device__ __forceinline__ void mma_tf32(float* c, const uint32_t* a, const uint32_t* b) {
    asm volatile(
        "mma.sync.aligned.m16n8k8.row.col.f32.tf32.tf32.f32 "
        "{%0,%1,%2,%3}, {%4,%5,%6,%7}, {%8,%9}, {%0,%1,%2,%3};"
        : "+f"(c[0]), "+f"(c[1]), "+f"(c[2]), "+f"(c[3])
        : "r"(a[0]), "r"(a[1]), "r"(a[2]), "r"(a[3]), "r"(b[0]), "r"(b[1]));
}

__device__ __forceinline__ void mma_f16(float* c, const uint32_t* a, const uint32_t* b) {
    asm volatile(
        "mma.sync.aligned.m16n8k16.row.col.f32.f16.f16.f32 "
        "{%0,%1,%2,%3}, {%4,%5,%6,%7}, {%8,%9}, {%0,%1,%2,%3};"
        : "+f"(c[0]), "+f"(c[1]), "+f"(c[2]), "+f"(c[3])
        : "r"(a[0]), "r"(a[1]), "r"(a[2]), "r"(a[3]), "r"(b[0]), "r"(b[1]));
}

// ---------------------------------------------------------------------------
// Convert kernels: fp32 -> fp16
// ---------------------------------------------------------------------------
__global__ void conv_spike(const float4* __restrict__ src)
{
    const size_t n4 = (size_t)MROWS * Ee / 4;
    __half2* dst = reinterpret_cast<__half2*>(g_spike_h);
    for (size_t i = blockIdx.x * (size_t)blockDim.x + threadIdx.x;
         i < n4; i += (size_t)gridDim.x * blockDim.x) {
        float4 v = src[i];
        dst[2 * i]     = __floats2half2_rn(v.x, v.y);
        dst[2 * i + 1] = __floats2half2_rn(v.z, v.w);
    }
}

__global__ void conv_w(const float4* __restrict__ Wk, const float4* __restrict__ Wv)
{
    int i = blockIdx.x * blockDim.x + threadIdx.x;   // < NKV*Ee/4 = 32768
    const int half1 = KVHD * Ee / 4;
    float4 v = (i < half1) ? Wk[i] : Wv[i - half1];
    __half2* dst = reinterpret_cast<__half2*>(g_wkv_h);
    dst[2 * i]     = __floats2half2_rn(v.x, v.y);
    dst[2 * i + 1] = __floats2half2_rn(v.z, v.w);
}

// ---------------------------------------------------------------------------
// K1: xq = (latent_query @ Wq^T) / sqrt(D)  (fp32)
// ---------------------------------------------------------------------------
__global__ void xq_kernel(const float* __restrict__ lq, const float* __restrict__ Wq)
{
    int l = blockIdx.x;
    __shared__ float qs[Ee];
    for (int e = threadIdx.x; e < Ee; e += blockDim.x) qs[e] = lq[l * Ee + e];
    __syncthreads();
    int j = threadIdx.x;
    const float* w = Wq + (size_t)j * Ee;
    float acc = 0.f;
#pragma unroll 8
    for (int e = 0; e < Ee; e++) acc += qs[e] * __ldg(&w[e]);
    g_xq[l * HD + j] = acc * 0.125f;
}

// ---------------------------------------------------------------------------
// K2: fp16 GEMM xkv = spike_h @ wkv_h^T, RoPE fused into epilogue (K half).
// CTA tile 128x128, BK=32 halves, 3-stage cp.async, 256 threads, 8 warps
// (4 m x 2 n), warp tile 32x64.  grid = (2, 1024): x=0 -> K cols, x=1 -> V.
// ---------------------------------------------------------------------------
#define STGB 20480
#define GEMM16_SMEM (3 * STGB)   // 61440 bytes

__global__ void __launch_bounds__(256, 2) gemm_kv_f16(
    const int* __restrict__ offs,
    const float* __restrict__ cosT,
    const float* __restrict__ sinT)
{
    extern __shared__ char sm_raw[];
    uint32_t sbase = (uint32_t)__cvta_generic_to_shared(sm_raw);

    int tid  = threadIdx.x;
    int wid  = tid >> 5, lane = tid & 31;
    int m0   = blockIdx.y * 128;
    int n0   = blockIdx.x * 128;
    int wm   = (wid & 3) * 32;
    int wn   = (wid >> 2) * 64;

    float acc[2][8][4];
#pragma unroll
    for (int mt = 0; mt < 2; mt++)
#pragma unroll
        for (int nt = 0; nt < 8; nt++)
#pragma unroll
            for (int j = 0; j < 4; j++) acc[mt][nt][j] = 0.f;

    int lrow = tid >> 1;            // 0..127
    int lch  = (tid & 1) * 2;       // chunk pair 0/2
    const __half* ag = g_spike_h + (size_t)(m0 + lrow) * Ee + lch * 8;
    const __half* bg = g_wkv_h   + (size_t)(n0 + lrow) * Ee + lch * 8;
    uint32_t dA = sbase + lrow * 80 + lch * 16;
    uint32_t dB = dA + 10240;

    auto issue = [&](int it) {
        uint32_t so = (uint32_t)(it % 3) * STGB;
        const __half* a = ag + it * 32;
        const __half* b = bg + it * 32;
        cp_async16(dA + so,      a);
        cp_async16(dA + so + 16, a + 8);
        cp_async16(dB + so,      b);
        cp_async16(dB + so + 16, b + 8);
    };

    issue(0); CP_COMMIT();
    issue(1); CP_COMMIT();

    for (int it = 0; it < 16; it++) {
        CP_WAIT(1);
        __syncthreads();
        if (it + 2 < 16) issue(it + 2);
        CP_COMMIT();

        uint32_t As = sbase + (uint32_t)(it % 3) * STGB;
        uint32_t Bs = As + 10240;
#pragma unroll
        for (int ks = 0; ks < 2; ks++) {
            int k0b = (ks * 16 + (lane & 3) * 2) * 2;   // byte offset in row
            uint32_t af[2][4], bf[8][2];
#pragma unroll
            for (int mt = 0; mt < 2; mt++) {
                uint32_t b0 = As + (uint32_t)(wm + mt * 16 + (lane >> 2)) * 80 + k0b;
                af[mt][0] = lds32(b0);
                af[mt][1] = lds32(b0 + 8 * 80);
                af[mt][2] = lds32(b0 + 16);
                af[mt][3] = lds32(b0 + 8 * 80 + 16);
            }
#pragma unroll
            for (int nt = 0; nt < 8; nt++) {
                uint32_t b0 = Bs + (uint32_t)(wn + nt * 8 + (lane >> 2)) * 80 + k0b;
                bf[nt][0] = lds32(b0);
                bf[nt][1] = lds32(b0 + 16);
            }
#pragma unroll
            for (int mt = 0; mt < 2; mt++)
#pragma unroll
                for (int nt = 0; nt < 8; nt++)
                    mma_f16(acc[mt][nt], af[mt], bf[nt]);
        }
    }

    // Epilogue -> fp16 xkv; RoPE on K half (blockIdx.x == 0)
    __half2* outp = reinterpret_cast<__half2*>(g_xkv_h);
    if (n0 == 0) {
#pragma unroll
        for (int mt = 0; mt < 2; mt++) {
            int r0 = m0 + wm + mt * 16 + (lane >> 2);
            int r1 = r0 + 8;
            int o0 = __ldg(&offs[r0]) * Dd;
            int o1 = __ldg(&offs[r1]) * Dd;
#pragma unroll
            for (int nt = 0; nt < 4; nt++) {
                int dbase = nt * 8 + (lane & 3) * 2;   // < 32
                float lo0[2], hi0[2], lo1[2], hi1[2];
#pragma unroll
                for (int j = 0; j < 2; j++) {
                    int d = dbase + j;
                    float c0 = __ldg(&cosT[o0 + d]), s0 = __ldg(&sinT[o0 + d]);
                    float c1 = __ldg(&cosT[o1 + d]), s1 = __ldg(&sinT[o1 + d]);
                    float u = acc[mt][nt][j],     v = acc[mt][nt + 4][j];
                    lo0[j] = u * c0 - v * s0;  hi0[j] = v * c0 + u * s0;
                    u = acc[mt][nt][j + 2];    v = acc[mt][nt + 4][j + 2];
                    lo1[j] = u * c1 - v * s1;  hi1[j] = v * c1 + u * s1;
                }
                int col = wn + nt * 8 + (lane & 3) * 2;   // 0..127 even
                outp[((size_t)r0 * NKV + col) >> 1]        = __floats2half2_rn(lo0[0], lo0[1]);
                outp[((size_t)r0 * NKV + col + 32) >> 1]   = __floats2half2_rn(hi0[0], hi0[1]);
                outp[((size_t)r1 * NKV + col) >> 1]        = __floats2half2_rn(lo1[0], lo1[1]);
                outp[((size_t)r1 * NKV + col + 32) >> 1]   = __floats2half2_rn(hi1[0], hi1[1]);
            }
        }
    } else {
#pragma unroll
        for (int mt = 0; mt < 2; mt++) {
            int r0 = m0 + wm + mt * 16 + (lane >> 2);
            int r1 = r0 + 8;
#pragma unroll
            for (int nt = 0; nt < 8; nt++) {
                int col = 128 + wn + nt * 8 + (lane & 3) * 2;
                outp[((size_t)r0 * NKV + col) >> 1] =
                    __floats2half2_rn(acc[mt][nt][0], acc[mt][nt][1]);
                outp[((size_t)r1 * NKV + col) >> 1] =
                    __floats2half2_rn(acc[mt][nt][2], acc[mt][nt][3]);
            }
        }
    }
}

// ---------------------------------------------------------------------------
// K3: attention. grid (kvh=2, bk=256), 256 threads.
// smem: scores fp32 [4h][16l][512s] (128KB) + V fp16 [512][64] (64KB)
//       + q fp32 [4h][16l][64d] (16KB) = 208KB dynamic.
// ---------------------------------------------------------------------------
#define ATTN_SMEM (4*16*512*4 + 512*64*2 + 4*16*64*4)   // 212992

__global__ void __launch_bounds__(256, 1) attn2(const int* __restrict__ slen)
{
    extern __shared__ char sm_raw[];
    float*  sc = (float*)sm_raw;                         // [4][16][512]
    __half* Vs = (__half*)(sm_raw + 131072);             // [512][64]
    float*  qs = (float*)(sm_raw + 131072 + 65536);      // [4][16][64]

    int kvh = blockIdx.x;
    int bk  = blockIdx.y;
    int tid = threadIdx.x;
    size_t base = (size_t)bk * Ss;

    // stage V via cp.async (overlaps with phase 1)
    {
        uint32_t vb = (uint32_t)__cvta_generic_to_shared(Vs);
#pragma unroll
        for (int i = 0; i < 16; i++) {
            int cid = tid + i * 256;
            int row = cid >> 3, ch = cid & 7;
            const __half* src = g_xkv_h + (base + row) * NKV + 128 + kvh * 64 + ch * 8;
            cp_async16(vb + (uint32_t)row * 128 + ch * 16, src);
        }
        CP_COMMIT();
    }
    // load q (fp32)
    for (int i = tid; i < 4 * 16 * 64; i += 256) {
        int hh = i >> 10, rem = i & 1023, l = rem >> 6, d = rem & 63;
        qs[i] = g_xq[l * HD + (kvh * 4 + hh) * Dd + d];
    }
    __syncthreads();

    int len = slen[bk];

    // Phase 1: scores for all 4 heads, K row loaded once per s
    for (int si = 0; si < 2; si++) {
        int s = tid + si * 256;
        const uint4* kp4 = (const uint4*)(g_xkv_h + (base + s) * NKV + kvh * 64);
        float kf[64];
#pragma unroll
        for (int c = 0; c < 8; c++) {
            uint4 u = __ldg(&kp4[c]);
            const __half2* h = (const __half2*)&u;
#pragma unroll
            for (int p = 0; p < 4; p++) {
                float2 f = __half22float2(h[p]);
                kf[c * 8 + p * 2]     = f.x;
                kf[c * 8 + p * 2 + 1] = f.y;
            }
        }
        bool valid = (s < len);
#pragma unroll
        for (int hh = 0; hh < 4; hh++) {
            for (int l = 0; l < Ll; l++) {
                const float* qrow = &qs[(hh * 16 + l) * 64];
                float a = 0.f;
#pragma unroll
                for (int d4 = 0; d4 < 64; d4 += 4) {
                    float4 q = *(const float4*)&qrow[d4];
                    a += kf[d4] * q.x + kf[d4 + 1] * q.y
                       + kf[d4 + 2] * q.z + kf[d4 + 3] * q.w;
                }
                sc[(hh * 16 + l) * 512 + s] = valid ? a : -CUDART_INF_F;
            }
        }
    }
    __syncthreads();

    // Phase 2: softmax (warp per row) over the 64 score rows
    int w = tid >> 5, lane = tid & 31;
    for (int row = w; row < 64; row += 8) {
        float* r = sc + row * 512;
        float mx = -CUDART_INF_F;
        for (int i = lane; i < 512; i += 32) mx = fmaxf(mx, r[i]);
#pragma unroll
        for (int off = 16; off; off >>= 1)
            mx = fmaxf(mx, __shfl_xor_sync(0xffffffffu, mx, off));
        float sum = 0.f;
        for (int i = lane; i < 512; i += 32) {
            float e = __expf(r[i] - mx);
            r[i] = e;
            sum += e;
        }
#pragma unroll
        for (int off = 16; off; off >>= 1)
            sum += __shfl_xor_sync(0xffffffffu, sum, off);
        float inv = 1.f / sum;
        for (int i = lane; i < 512; i += 32) r[i] *= inv;
    }
    CP_WAIT(0);
    __syncthreads();

    // Phase 3: AV. thread -> (h2, l, dg); handles heads h2 and h2+2.
    {
        int h2 = tid >> 7;
        int l  = (tid >> 3) & 15;
        int dg = tid & 7;
        float o0[8], o1[8];
#pragma unroll
        for (int j = 0; j < 8; j++) { o0[j] = 0.f; o1[j] = 0.f; }
        const float* s0 = sc + (h2 * 16 + l) * 512;
        const float* s1 = sc + ((h2 + 2) * 16 + l) * 512;
        const __half* vrow = Vs + dg * 8;
        for (int s = 0; s < 512; s++) {
            uint4 u = *(const uint4*)(vrow + s * 64);
            const __half2* h = (const __half2*)&u;
            float a0 = s0[s], a1 = s1[s];
#pragma unroll
            for (int p = 0; p < 4; p++) {
                float2 f = __half22float2(h[p]);
                o0[p * 2]     += a0 * f.x;  o0[p * 2 + 1] += a0 * f.y;
                o1[p * 2]     += a1 * f.x;  o1[p * 2 + 1] += a1 * f.y;
            }
        }
        int hA = kvh * 4 + h2, hB = kvh * 4 + h2 + 2;
        float* dA = g_att + (((size_t)bk * Ll + l) * Hh + hA) * Dd + dg * 8;
        float* dB = g_att + (((size_t)bk * Ll + l) * Hh + hB) * Dd + dg * 8;
        *(float4*)dA       = make_float4(o0[0], o0[1], o0[2], o0[3]);
        *(float4*)(dA + 4) = make_float4(o0[4], o0[5], o0[6], o0[7]);
        *(float4*)dB       = make_float4(o1[0], o1[1], o1[2], o1[3]);
        *(float4*)(dB + 4) = make_float4(o1[4], o1[5], o1[6], o1[7]);
    }
}

// ---------------------------------------------------------------------------
// K4: tf32 NT GEMM for out = att @ Wo^T
// ---------------------------------------------------------------------------
#define PADW 20

__global__ void __launch_bounds__(256, 2) gemm_mma(
    const float* __restrict__ A,
    const float* __restrict__ B0,
    const float* __restrict__ B1,
    int nsplit,
    float* __restrict__ C,
    int N, int Kd)
{
    __shared__ float As[2][128 * PADW];
    __shared__ float Bs[2][128 * PADW];

    int tid  = threadIdx.x;
    int wid  = tid >> 5, lane = tid & 31;
    int m0   = blockIdx.y * 128;
    int n0   = blockIdx.x * 128;
    int wm   = (wid & 3) * 32;
    int wn   = (wid >> 2) * 64;

    float acc[2][8][4];
#pragma unroll
    for (int mt = 0; mt < 2; mt++)
#pragma unroll
        for (int nt = 0; nt < 8; nt++)
#pragma unroll
            for (int j = 0; j < 4; j++) acc[mt][nt][j] = 0.f;

    int ldrow = tid >> 2;
    int ldc   = (tid & 3) * 4;

    const float* ag0 = A + (size_t)(m0 + ldrow)      * Kd + ldc;
    const float* ag1 = A + (size_t)(m0 + ldrow + 64) * Kd + ldc;
    int nr0 = n0 + ldrow, nr1 = n0 + ldrow + 64;
    const float* bg0 = ((nr0 < nsplit) ? B0 + (size_t)nr0 * Kd
                                       : B1 + (size_t)(nr0 - nsplit) * Kd) + ldc;
    const float* bg1 = ((nr1 < nsplit) ? B0 + (size_t)nr1 * Kd
                                       : B1 + (size_t)(nr1 - nsplit) * Kd) + ldc;

    uint32_t sa_base = (uint32_t)__cvta_generic_to_shared(&As[0][0]);
    uint32_t sb_base = (uint32_t)__cvta_generic_to_shared(&Bs[0][0]);
    uint32_t stg_sz  = 128 * PADW * 4;
    uint32_t dA0 = sa_base + ((uint32_t)ldrow * PADW + ldc) * 4;
    uint32_t dA1 = sa_base + ((uint32_t)(ldrow + 64) * PADW + ldc) * 4;
    uint32_t dB0 = sb_base + ((uint32_t)ldrow * PADW + ldc) * 4;
    uint32_t dB1 = sb_base + ((uint32_t)(ldrow + 64) * PADW + ldc) * 4;

    int NIT = Kd >> 4;

    cp_async16(dA0, ag0); cp_async16(dA1, ag1);
    cp_async16(dB0, bg0); cp_async16(dB1, bg1);
    CP_COMMIT();

    for (int it = 0; it < NIT; it++) {
        int cur = it & 1;
        if (it + 1 < NIT) {
            int nk  = (it + 1) << 4;
            uint32_t so = (uint32_t)((it + 1) & 1) * stg_sz;
            cp_async16(dA0 + so, ag0 + nk); cp_async16(dA1 + so, ag1 + nk);
            cp_async16(dB0 + so, bg0 + nk); cp_async16(dB1 + so, bg1 + nk);
            CP_COMMIT();
            CP_WAIT(1);
        } else {
            CP_WAIT(0);
        }
        __syncthreads();

        const float* as = As[cur];
        const float* bs = Bs[cur];
#pragma unroll
        for (int ks = 0; ks < 2; ks++) {
            int k0 = ks * 8 + (lane & 3);
            uint32_t af[2][4], bf[8][2];
#pragma unroll
            for (int mt = 0; mt < 2; mt++) {
                int r = wm + mt * 16 + (lane >> 2);
                af[mt][0] = f2tf32(as[r * PADW + k0]);
                af[mt][1] = f2tf32(as[(r + 8) * PADW + k0]);
                af[mt][2] = f2tf32(as[r * PADW + k0 + 4]);
                af[mt][3] = f2tf32(as[(r + 8) * PADW + k0 + 4]);
            }
#pragma unroll
            for (int nt = 0; nt < 8; nt++) {
                int n = wn + nt * 8 + (lane >> 2);
                bf[nt][0] = f2tf32(bs[n * PADW + k0]);
                bf[nt][1] = f2tf32(bs[n * PADW + k0 + 4]);
            }
#pragma unroll
            for (int mt = 0; mt < 2; mt++)
#pragma unroll
                for (int nt = 0; nt < 8; nt++)
                    mma_tf32(acc[mt][nt], af[mt], bf[nt]);
        }
        __syncthreads();
    }

#pragma unroll
    for (int mt = 0; mt < 2; mt++) {
        int row = m0 + wm + mt * 16 + (lane >> 2);
#pragma unroll
        for (int nt = 0; nt < 8; nt++) {
            int col = n0 + wn + nt * 8 + (lane & 3) * 2;
            *reinterpret_cast<float2*>(C + (size_t)row * N + col) =
                make_float2(acc[mt][nt][0], acc[mt][nt][1]);
            *reinterpret_cast<float2*>(C + (size_t)(row + 8) * N + col) =
                make_float2(acc[mt][nt][2], acc[mt][nt][3]);
        }
    }
}

// ---------------------------------------------------------------------------
extern "C" void kernel_launch(void* const* d_in, const int* in_sizes, int n_in,
                              void* d_out, int out_size)
{
    const float* spike  = (const float*)d_in[0];
    const int*   offs   = (const int*)  d_in[1];
    const int*   slen   = (const int*)  d_in[2];
    const float* cosT   = (const float*)d_in[3];
    const float* sinT   = (const float*)d_in[4];
    const float* lq     = (const float*)d_in[5];
    const float* Wq     = (const float*)d_in[6];
    const float* Wk     = (const float*)d_in[7];
    const float* Wv     = (const float*)d_in[8];
    const float* Wo     = (const float*)d_in[9];
    float* out = (float*)d_out;

    void* att_p = nullptr;
    cudaGetSymbolAddress(&att_p, g_att);

    cudaFuncSetAttribute(gemm_kv_f16,
                         cudaFuncAttributeMaxDynamicSharedMemorySize, GEMM16_SMEM);
    cudaFuncSetAttribute(attn2,
                         cudaFuncAttributeMaxDynamicSharedMemorySize, ATTN_SMEM);

    // Convert inputs to fp16
    conv_spike<<<4096, 256>>>((const float4*)spike);
    conv_w<<<128, 256>>>((const float4*)Wk, (const float4*)Wv);

    // K1: queries
    xq_kernel<<<Ll, Ee>>>(lq, Wq);

    // K2: fp16 K|V projection with fused RoPE epilogue
    gemm_kv_f16<<<dim3(2, MROWS / 128), 256, GEMM16_SMEM>>>(offs, cosT, sinT);

    // K3: attention
    attn2<<<dim3(KVHn, BKTOT), 256, ATTN_SMEM>>>(slen);

    // K4: output projection (tf32)
    gemm_mma<<<dim3(Ee / 128, (BKTOT * Ll) / 128), 256>>>(
        (const float*)att_p, Wo, Wo, 1 << 30, out, Ee, HD);
}

// round 6
// speedup vs baseline: 3.8330x; 1.4342x over previous
#include <cuda_runtime.h>
#include <cuda_fp16.h>
#include <math.h>
#include <math_constants.h>
#include <stdint.h>

// Problem constants
#define Bb   16
#define Kk   16
#define Ss   512
#define Ee   512
#define Ll   16
#define Hh   8
#define KVHn 2
#define Dd   64
#define HD   (Hh*Dd)        // 512
#define KVHD (KVHn*Dd)      // 128
#define NKV  (2*KVHD)       // 256
#define BKTOT (Bb*Kk)       // 256
#define MROWS (BKTOT*Ss)    // 131072

// Scratch (static device globals)
__device__ __half g_spike_h[(size_t)MROWS * Ee];   // fp16 spike
__device__ __half g_wkv_h[NKV * Ee];               // [Wk;Wv] fp16
__device__ __half g_xkv_h[(size_t)MROWS * NKV];    // K(rope'd)|V fp16
__device__ __half g_xq_h[KVHn * 64 * Dd];          // q fp16 [kvh][hh*16+l][d], pre-scaled
__device__ float  g_att[(size_t)BKTOT * Ll * HD];  // attention out fp32

// ---------------------------------------------------------------------------
// PTX helpers
// ---------------------------------------------------------------------------
__device__ __forceinline__ void cp_async16(uint32_t saddr, const void* gptr) {
    asm volatile("cp.async.cg.shared.global [%0], [%1], 16;"
                 :: "r"(saddr), "l"(gptr) : "memory");
}
#define CP_COMMIT() asm volatile("cp.async.commit_group;" ::: "memory")
#define CP_WAIT(n)  asm volatile("cp.async.wait_group %0;" :: "n"(n) : "memory")

__device__ __forceinline__ uint32_t lds32(uint32_t addr) {
    uint32_t v;
    asm volatile("ld.shared.b32 %0, [%1];" : "=r"(v) : "r"(addr));
    return v;
}

__device__ __forceinline__ uint32_t f2tf32(float f) {
    uint32_t r;
    asm("cvt.rna.tf32.f32 %0, %1;" : "=r"(r) : "f"(f));
    return r;
}

__device__ __forceinline__ void mma_tf32(float* c, const uint32_t* a, const uint32_t* b) {
    asm volatile(
        "mma.sync.aligned.m16n8k8.row.col.f32.tf32.tf32.f32 "
        "{%0,%1,%2,%3}, {%4,%5,%6,%7}, {%8,%9}, {%0,%1,%2,%3};"
        : "+f"(c[0]), "+f"(c[1]), "+f"(c[2]), "+f"(c[3])
        : "r"(a[0]), "r"(a[1]), "r"(a[2]), "r"(a[3]), "r"(b[0]), "r"(b[1]));
}

__device__ __forceinline__ void mma_f16(float* c, const uint32_t* a, const uint32_t* b) {
    asm volatile(
        "mma.sync.aligned.m16n8k16.row.col.f32.f16.f16.f32 "
        "{%0,%1,%2,%3}, {%4,%5,%6,%7}, {%8,%9}, {%0,%1,%2,%3};"
        : "+f"(c[0]), "+f"(c[1]), "+f"(c[2]), "+f"(c[3])
        : "r"(a[0]), "r"(a[1]), "r"(a[2]), "r"(a[3]), "r"(b[0]), "r"(b[1]));
}

__device__ __forceinline__ void ldsm_x4(uint32_t* r, uint32_t addr) {
    asm volatile("ldmatrix.sync.aligned.m8n8.x4.shared.b16 {%0,%1,%2,%3}, [%4];"
        : "=r"(r[0]), "=r"(r[1]), "=r"(r[2]), "=r"(r[3]) : "r"(addr));
}
__device__ __forceinline__ void ldsm_x4_t(uint32_t* r, uint32_t addr) {
    asm volatile("ldmatrix.sync.aligned.m8n8.x4.trans.shared.b16 {%0,%1,%2,%3}, [%4];"
        : "=r"(r[0]), "=r"(r[1]), "=r"(r[2]), "=r"(r[3]) : "r"(addr));
}

// ---------------------------------------------------------------------------
// Convert kernels: fp32 -> fp16
// ---------------------------------------------------------------------------
__global__ void conv_spike(const float4* __restrict__ src)
{
    const size_t n4 = (size_t)MROWS * Ee / 4;
    __half2* dst = reinterpret_cast<__half2*>(g_spike_h);
    for (size_t i = blockIdx.x * (size_t)blockDim.x + threadIdx.x;
         i < n4; i += (size_t)gridDim.x * blockDim.x) {
        float4 v = src[i];
        dst[2 * i]     = __floats2half2_rn(v.x, v.y);
        dst[2 * i + 1] = __floats2half2_rn(v.z, v.w);
    }
}

__global__ void conv_w(const float4* __restrict__ Wk, const float4* __restrict__ Wv)
{
    int i = blockIdx.x * blockDim.x + threadIdx.x;   // < NKV*Ee/4 = 32768
    const int half1 = KVHD * Ee / 4;
    float4 v = (i < half1) ? Wk[i] : Wv[i - half1];
    __half2* dst = reinterpret_cast<__half2*>(g_wkv_h);
    dst[2 * i]     = __floats2half2_rn(v.x, v.y);
    dst[2 * i + 1] = __floats2half2_rn(v.z, v.w);
}

// ---------------------------------------------------------------------------
// K1: xq = (latent_query @ Wq^T) / sqrt(D), stored fp16 grouped by kvh
// ---------------------------------------------------------------------------
__global__ void xq_kernel(const float* __restrict__ lq, const float* __restrict__ Wq)
{
    int l = blockIdx.x;
    __shared__ float qs[Ee];
    for (int e = threadIdx.x; e < Ee; e += blockDim.x) qs[e] = lq[l * Ee + e];
    __syncthreads();
    int j = threadIdx.x;
    const float* w = Wq + (size_t)j * Ee;
    float acc = 0.f;
#pragma unroll 8
    for (int e = 0; e < Ee; e++) acc += qs[e] * __ldg(&w[e]);
    int h = j >> 6, d = j & 63;
    g_xq_h[((h >> 2) * 64 + (h & 3) * 16 + l) * 64 + d] = __float2half(acc * 0.125f);
}

// ---------------------------------------------------------------------------
// K2: fp16 GEMM xkv = spike_h @ wkv_h^T, RoPE fused into epilogue (K half).
// (unchanged from R5)
// ---------------------------------------------------------------------------
#define STGB 20480
#define GEMM16_SMEM (3 * STGB)   // 61440 bytes

__global__ void __launch_bounds__(256, 2) gemm_kv_f16(
    const int* __restrict__ offs,
    const float* __restrict__ cosT,
    const float* __restrict__ sinT)
{
    extern __shared__ char sm_raw[];
    uint32_t sbase = (uint32_t)__cvta_generic_to_shared(sm_raw);

    int tid  = threadIdx.x;
    int wid  = tid >> 5, lane = tid & 31;
    int m0   = blockIdx.y * 128;
    int n0   = blockIdx.x * 128;
    int wm   = (wid & 3) * 32;
    int wn   = (wid >> 2) * 64;

    float acc[2][8][4];
#pragma unroll
    for (int mt = 0; mt < 2; mt++)
#pragma unroll
        for (int nt = 0; nt < 8; nt++)
#pragma unroll
            for (int j = 0; j < 4; j++) acc[mt][nt][j] = 0.f;

    int lrow = tid >> 1;
    int lch  = (tid & 1) * 2;
    const __half* ag = g_spike_h + (size_t)(m0 + lrow) * Ee + lch * 8;
    const __half* bg = g_wkv_h   + (size_t)(n0 + lrow) * Ee + lch * 8;
    uint32_t dA = sbase + lrow * 80 + lch * 16;
    uint32_t dB = dA + 10240;

    auto issue = [&](int it) {
        uint32_t so = (uint32_t)(it % 3) * STGB;
        const __half* a = ag + it * 32;
        const __half* b = bg + it * 32;
        cp_async16(dA + so,      a);
        cp_async16(dA + so + 16, a + 8);
        cp_async16(dB + so,      b);
        cp_async16(dB + so + 16, b + 8);
    };

    issue(0); CP_COMMIT();
    issue(1); CP_COMMIT();

    for (int it = 0; it < 16; it++) {
        CP_WAIT(1);
        __syncthreads();
        if (it + 2 < 16) issue(it + 2);
        CP_COMMIT();

        uint32_t As = sbase + (uint32_t)(it % 3) * STGB;
        uint32_t Bs = As + 10240;
#pragma unroll
        for (int ks = 0; ks < 2; ks++) {
            int k0b = (ks * 16 + (lane & 3) * 2) * 2;
            uint32_t af[2][4], bf[8][2];
#pragma unroll
            for (int mt = 0; mt < 2; mt++) {
                uint32_t b0 = As + (uint32_t)(wm + mt * 16 + (lane >> 2)) * 80 + k0b;
                af[mt][0] = lds32(b0);
                af[mt][1] = lds32(b0 + 8 * 80);
                af[mt][2] = lds32(b0 + 16);
                af[mt][3] = lds32(b0 + 8 * 80 + 16);
            }
#pragma unroll
            for (int nt = 0; nt < 8; nt++) {
                uint32_t b0 = Bs + (uint32_t)(wn + nt * 8 + (lane >> 2)) * 80 + k0b;
                bf[nt][0] = lds32(b0);
                bf[nt][1] = lds32(b0 + 16);
            }
#pragma unroll
            for (int mt = 0; mt < 2; mt++)
#pragma unroll
                for (int nt = 0; nt < 8; nt++)
                    mma_f16(acc[mt][nt], af[mt], bf[nt]);
        }
    }

    __half2* outp = reinterpret_cast<__half2*>(g_xkv_h);
    if (n0 == 0) {
#pragma unroll
        for (int mt = 0; mt < 2; mt++) {
            int r0 = m0 + wm + mt * 16 + (lane >> 2);
            int r1 = r0 + 8;
            int o0 = __ldg(&offs[r0]) * Dd;
            int o1 = __ldg(&offs[r1]) * Dd;
#pragma unroll
            for (int nt = 0; nt < 4; nt++) {
                int dbase = nt * 8 + (lane & 3) * 2;
                float lo0[2], hi0[2], lo1[2], hi1[2];
#pragma unroll
                for (int j = 0; j < 2; j++) {
                    int d = dbase + j;
                    float c0 = __ldg(&cosT[o0 + d]), s0 = __ldg(&sinT[o0 + d]);
                    float c1 = __ldg(&cosT[o1 + d]), s1 = __ldg(&sinT[o1 + d]);
                    float u = acc[mt][nt][j],     v = acc[mt][nt + 4][j];
                    lo0[j] = u * c0 - v * s0;  hi0[j] = v * c0 + u * s0;
                    u = acc[mt][nt][j + 2];    v = acc[mt][nt + 4][j + 2];
                    lo1[j] = u * c1 - v * s1;  hi1[j] = v * c1 + u * s1;
                }
                int col = wn + nt * 8 + (lane & 3) * 2;
                outp[((size_t)r0 * NKV + col) >> 1]        = __floats2half2_rn(lo0[0], lo0[1]);
                outp[((size_t)r0 * NKV + col + 32) >> 1]   = __floats2half2_rn(hi0[0], hi0[1]);
                outp[((size_t)r1 * NKV + col) >> 1]        = __floats2half2_rn(lo1[0], lo1[1]);
                outp[((size_t)r1 * NKV + col + 32) >> 1]   = __floats2half2_rn(hi1[0], hi1[1]);
            }
        }
    } else {
#pragma unroll
        for (int mt = 0; mt < 2; mt++) {
            int r0 = m0 + wm + mt * 16 + (lane >> 2);
            int r1 = r0 + 8;
#pragma unroll
            for (int nt = 0; nt < 8; nt++) {
                int col = 128 + wn + nt * 8 + (lane & 3) * 2;
                outp[((size_t)r0 * NKV + col) >> 1] =
                    __floats2half2_rn(acc[mt][nt][0], acc[mt][nt][1]);
                outp[((size_t)r1 * NKV + col) >> 1] =
                    __floats2half2_rn(acc[mt][nt][2], acc[mt][nt][3]);
            }
        }
    }
}

// ---------------------------------------------------------------------------
// K3: tensor-core attention. grid (kvh=2, bk=256), 256 threads = 8 warps.
// Warp (mt = wid&3, nh = wid>>2): m-tile 16 rows (h*16+l), n-half.
// Phase 1: S[64,512] = q[64,64] @ K^T, scores in registers.
// Softmax in registers (quad shfl + smem cross-half), probs -> fp16 P
// (reusing K's smem), normalization deferred to epilogue.
// Phase 2: out[64,64] = P @ V via mma with ldmatrix.trans on V.
// smem: K/P 512*144=73728 | V 73728 | q 64*144=9216 | red 1024 -> 157696 B
// ---------------------------------------------------------------------------
#define KOFF 0
#define VOFF 73728
#define QOFF 147456
#define ROFF 156672
#define ATTN3_SMEM (ROFF + 1024)

__global__ void __launch_bounds__(256, 1) attn3(const int* __restrict__ slen)
{
    extern __shared__ char sm[];
    uint32_t sb = (uint32_t)__cvta_generic_to_shared(sm);
    int tid = threadIdx.x, lane = tid & 31, wid = tid >> 5;
    int kvh = blockIdx.x, bk = blockIdx.y;
    size_t base = (size_t)bk * Ss;
    int mt = wid & 3, nh = wid >> 2;
    int m0 = mt * 16;

    // K + q -> group 0; V -> group 1
#pragma unroll
    for (int i = 0; i < 16; i++) {
        int cid = tid + i * 256; int row = cid >> 3, ch = cid & 7;
        cp_async16(sb + KOFF + row * 144 + ch * 16,
                   g_xkv_h + (base + row) * NKV + kvh * 64 + ch * 8);
    }
#pragma unroll
    for (int i = 0; i < 2; i++) {
        int cid = tid + i * 256; int row = cid >> 3, ch = cid & 7;
        cp_async16(sb + QOFF + row * 144 + ch * 16,
                   g_xq_h + (kvh * 64 + row) * 64 + ch * 8);
    }
    CP_COMMIT();
#pragma unroll
    for (int i = 0; i < 16; i++) {
        int cid = tid + i * 256; int row = cid >> 3, ch = cid & 7;
        cp_async16(sb + VOFF + row * 144 + ch * 16,
                   g_xkv_h + (base + row) * NKV + 128 + kvh * 64 + ch * 8);
    }
    CP_COMMIT();

    int len = slen[bk];

    CP_WAIT(1);
    __syncthreads();

    // ---- Phase 1: S = q @ K^T ----
    float acc[32][4];
#pragma unroll
    for (int nf = 0; nf < 32; nf++)
#pragma unroll
        for (int j = 0; j < 4; j++) acc[nf][j] = 0.f;

    uint32_t aab = sb + QOFF + (uint32_t)(m0 + (lane & 15)) * 144 + (lane >> 4) * 16;
#pragma unroll
    for (int kt = 0; kt < 4; kt++) {
        uint32_t a[4];
        ldsm_x4(a, aab + kt * 32);
#pragma unroll
        for (int np = 0; np < 16; np++) {
            uint32_t b[4];
            ldsm_x4(b, sb + KOFF + (uint32_t)(nh * 256 + np * 16 + (lane & 15)) * 144
                         + kt * 32 + (lane >> 4) * 16);
            uint32_t bp0[2] = {b[0], b[2]}, bp1[2] = {b[1], b[3]};
            mma_f16(acc[2 * np],     a, bp0);
            mma_f16(acc[2 * np + 1], a, bp1);
        }
    }

    // ---- Softmax (ragged mask; registers + quad shfl + smem cross-half) ----
    int scol = nh * 256 + (lane & 3) * 2;
    float mx0 = -CUDART_INF_F, mx1 = -CUDART_INF_F;
#pragma unroll
    for (int nf = 0; nf < 32; nf++) {
        int s0 = scol + nf * 8;
        if (s0 >= len)     { acc[nf][0] = -CUDART_INF_F; acc[nf][2] = -CUDART_INF_F; }
        if (s0 + 1 >= len) { acc[nf][1] = -CUDART_INF_F; acc[nf][3] = -CUDART_INF_F; }
        mx0 = fmaxf(mx0, fmaxf(acc[nf][0], acc[nf][1]));
        mx1 = fmaxf(mx1, fmaxf(acc[nf][2], acc[nf][3]));
    }
    mx0 = fmaxf(mx0, __shfl_xor_sync(0xffffffffu, mx0, 1));
    mx0 = fmaxf(mx0, __shfl_xor_sync(0xffffffffu, mx0, 2));
    mx1 = fmaxf(mx1, __shfl_xor_sync(0xffffffffu, mx1, 1));
    mx1 = fmaxf(mx1, __shfl_xor_sync(0xffffffffu, mx1, 2));

    float* redm = (float*)(sm + ROFF);       // [64][2] max
    float* reds = redm + 128;                // [64][2] sum
    int r0 = m0 + (lane >> 2), r1 = r0 + 8;
    if ((lane & 3) == 0) { redm[r0 * 2 + nh] = mx0; redm[r1 * 2 + nh] = mx1; }
    __syncthreads();                          // also: all K reads complete
    mx0 = fmaxf(redm[r0 * 2], redm[r0 * 2 + 1]);
    mx1 = fmaxf(redm[r1 * 2], redm[r1 * 2 + 1]);

    float sum0 = 0.f, sum1 = 0.f;
#pragma unroll
    for (int nf = 0; nf < 32; nf++) {
        acc[nf][0] = __expf(acc[nf][0] - mx0);
        acc[nf][1] = __expf(acc[nf][1] - mx0);
        acc[nf][2] = __expf(acc[nf][2] - mx1);
        acc[nf][3] = __expf(acc[nf][3] - mx1);
        sum0 += acc[nf][0] + acc[nf][1];
        sum1 += acc[nf][2] + acc[nf][3];
    }
    sum0 += __shfl_xor_sync(0xffffffffu, sum0, 1);
    sum0 += __shfl_xor_sync(0xffffffffu, sum0, 2);
    sum1 += __shfl_xor_sync(0xffffffffu, sum1, 1);
    sum1 += __shfl_xor_sync(0xffffffffu, sum1, 2);
    if ((lane & 3) == 0) { reds[r0 * 2 + nh] = sum0; reds[r1 * 2 + nh] = sum1; }
    __syncthreads();
    float inv0 = 1.f / (reds[r0 * 2] + reds[r0 * 2 + 1]);
    float inv1 = 1.f / (reds[r1 * 2] + reds[r1 * 2 + 1]);

    // ---- Write unnormalized probs fp16 into P (reuses K region) ----
#pragma unroll
    for (int nf = 0; nf < 32; nf++) {
        int s2 = scol + nf * 8;
        *(__half2*)(sm + KOFF + (size_t)r0 * 1040 + s2 * 2) =
            __floats2half2_rn(acc[nf][0], acc[nf][1]);
        *(__half2*)(sm + KOFF + (size_t)r1 * 1040 + s2 * 2) =
            __floats2half2_rn(acc[nf][2], acc[nf][3]);
    }
    CP_WAIT(0);
    __syncthreads();                          // P visible, V ready

    // ---- Phase 2: out = P @ V ----
    float oc[4][4];
#pragma unroll
    for (int i = 0; i < 4; i++)
#pragma unroll
        for (int j = 0; j < 4; j++) oc[i][j] = 0.f;

    uint32_t pab = sb + KOFF + (uint32_t)(m0 + (lane & 15)) * 1040 + (lane >> 4) * 16;
    int dbase = nh * 32;
#pragma unroll 4
    for (int kt = 0; kt < 32; kt++) {
        uint32_t a[4];
        ldsm_x4(a, pab + kt * 32);
        uint32_t vaddr = sb + VOFF + (uint32_t)(kt * 16 + (lane & 15)) * 144
                       + (dbase + (lane >> 4) * 8) * 2;
        uint32_t b[4];
        ldsm_x4_t(b, vaddr);
        {
            uint32_t bp0[2] = {b[0], b[1]}, bp1[2] = {b[2], b[3]};
            mma_f16(oc[0], a, bp0);
            mma_f16(oc[1], a, bp1);
        }
        ldsm_x4_t(b, vaddr + 32);
        {
            uint32_t bp0[2] = {b[0], b[1]}, bp1[2] = {b[2], b[3]};
            mma_f16(oc[2], a, bp0);
            mma_f16(oc[3], a, bp1);
        }
    }

    // ---- Epilogue: normalize + store ----
    float* orow0 = g_att + (((size_t)bk * Ll + (r0 & 15)) * Hh + kvh * 4 + (r0 >> 4)) * Dd;
    float* orow1 = g_att + (((size_t)bk * Ll + (r1 & 15)) * Hh + kvh * 4 + (r1 >> 4)) * Dd;
#pragma unroll
    for (int nf = 0; nf < 4; nf++) {
        int d = dbase + nf * 8 + (lane & 3) * 2;
        *(float2*)(orow0 + d) = make_float2(oc[nf][0] * inv0, oc[nf][1] * inv0);
        *(float2*)(orow1 + d) = make_float2(oc[nf][2] * inv1, oc[nf][3] * inv1);
    }
}

// ---------------------------------------------------------------------------
// K4: tf32 NT GEMM for out = att @ Wo^T  (unchanged)
// ---------------------------------------------------------------------------
#define PADW 20

__global__ void __launch_bounds__(256, 2) gemm_mma(
    const float* __restrict__ A,
    const float* __restrict__ B0,
    const float* __restrict__ B1,
    int nsplit,
    float* __restrict__ C,
    int N, int Kd)
{
    __shared__ float As[2][128 * PADW];
    __shared__ float Bs[2][128 * PADW];

    int tid  = threadIdx.x;
    int wid  = tid >> 5, lane = tid & 31;
    int m0   = blockIdx.y * 128;
    int n0   = blockIdx.x * 128;
    int wm   = (wid & 3) * 32;
    int wn   = (wid >> 2) * 64;

    float acc[2][8][4];
#pragma unroll
    for (int mt = 0; mt < 2; mt++)
#pragma unroll
        for (int nt = 0; nt < 8; nt++)
#pragma unroll
            for (int j = 0; j < 4; j++) acc[mt][nt][j] = 0.f;

    int ldrow = tid >> 2;
    int ldc   = (tid & 3) * 4;

    const float* ag0 = A + (size_t)(m0 + ldrow)      * Kd + ldc;
    const float* ag1 = A + (size_t)(m0 + ldrow + 64) * Kd + ldc;
    int nr0 = n0 + ldrow, nr1 = n0 + ldrow + 64;
    const float* bg0 = ((nr0 < nsplit) ? B0 + (size_t)nr0 * Kd
                                       : B1 + (size_t)(nr0 - nsplit) * Kd) + ldc;
    const float* bg1 = ((nr1 < nsplit) ? B0 + (size_t)nr1 * Kd
                                       : B1 + (size_t)(nr1 - nsplit) * Kd) + ldc;

    uint32_t sa_base = (uint32_t)__cvta_generic_to_shared(&As[0][0]);
    uint32_t sb_base = (uint32_t)__cvta_generic_to_shared(&Bs[0][0]);
    uint32_t stg_sz  = 128 * PADW * 4;
    uint32_t dA0 = sa_base + ((uint32_t)ldrow * PADW + ldc) * 4;
    uint32_t dA1 = sa_base + ((uint32_t)(ldrow + 64) * PADW + ldc) * 4;
    uint32_t dB0 = sb_base + ((uint32_t)ldrow * PADW + ldc) * 4;
    uint32_t dB1 = sb_base + ((uint32_t)(ldrow + 64) * PADW + ldc) * 4;

    int NIT = Kd >> 4;

    cp_async16(dA0, ag0); cp_async16(dA1, ag1);
    cp_async16(dB0, bg0); cp_async16(dB1, bg1);
    CP_COMMIT();

    for (int it = 0; it < NIT; it++) {
        int cur = it & 1;
        if (it + 1 < NIT) {
            int nk  = (it + 1) << 4;
            uint32_t so = (uint32_t)((it + 1) & 1) * stg_sz;
            cp_async16(dA0 + so, ag0 + nk); cp_async16(dA1 + so, ag1 + nk);
            cp_async16(dB0 + so, bg0 + nk); cp_async16(dB1 + so, bg1 + nk);
            CP_COMMIT();
            CP_WAIT(1);
        } else {
            CP_WAIT(0);
        }
        __syncthreads();

        const float* as = As[cur];
        const float* bs = Bs[cur];
#pragma unroll
        for (int ks = 0; ks < 2; ks++) {
            int k0 = ks * 8 + (lane & 3);
            uint32_t af[2][4], bf[8][2];
#pragma unroll
            for (int mt = 0; mt < 2; mt++) {
                int r = wm + mt * 16 + (lane >> 2);
                af[mt][0] = f2tf32(as[r * PADW + k0]);
                af[mt][1] = f2tf32(as[(r + 8) * PADW + k0]);
                af[mt][2] = f2tf32(as[r * PADW + k0 + 4]);
                af[mt][3] = f2tf32(as[(r + 8) * PADW + k0 + 4]);
            }
#pragma unroll
            for (int nt = 0; nt < 8; nt++) {
                int n = wn + nt * 8 + (lane >> 2);
                bf[nt][0] = f2tf32(bs[n * PADW + k0]);
                bf[nt][1] = f2tf32(bs[n * PADW + k0 + 4]);
            }
#pragma unroll
            for (int mt = 0; mt < 2; mt++)
#pragma unroll
                for (int nt = 0; nt < 8; nt++)
                    mma_tf32(acc[mt][nt], af[mt], bf[nt]);
        }
        __syncthreads();
    }

#pragma unroll
    for (int mt = 0; mt < 2; mt++) {
        int row = m0 + wm + mt * 16 + (lane >> 2);
#pragma unroll
        for (int nt = 0; nt < 8; nt++) {
            int col = n0 + wn + nt * 8 + (lane & 3) * 2;
            *reinterpret_cast<float2*>(C + (size_t)row * N + col) =
                make_float2(acc[mt][nt][0], acc[mt][nt][1]);
            *reinterpret_cast<float2*>(C + (size_t)(row + 8) * N + col) =
                make_float2(acc[mt][nt][2], acc[mt][nt][3]);
        }
    }
}

// ---------------------------------------------------------------------------
extern "C" void kernel_launch(void* const* d_in, const int* in_sizes, int n_in,
                              void* d_out, int out_size)
{
    const float* spike  = (const float*)d_in[0];
    const int*   offs   = (const int*)  d_in[1];
    const int*   slen   = (const int*)  d_in[2];
    const float* cosT   = (const float*)d_in[3];
    const float* sinT   = (const float*)d_in[4];
    const float* lq     = (const float*)d_in[5];
    const float* Wq     = (const float*)d_in[6];
    const float* Wk     = (const float*)d_in[7];
    const float* Wv     = (const float*)d_in[8];
    const float* Wo     = (const float*)d_in[9];
    float* out = (float*)d_out;

    void* att_p = nullptr;
    cudaGetSymbolAddress(&att_p, g_att);

    cudaFuncSetAttribute(gemm_kv_f16,
                         cudaFuncAttributeMaxDynamicSharedMemorySize, GEMM16_SMEM);
    cudaFuncSetAttribute(attn3,
                         cudaFuncAttributeMaxDynamicSharedMemorySize, ATTN3_SMEM);

    // Convert inputs to fp16
    conv_spike<<<4096, 256>>>((const float4*)spike);
    conv_w<<<128, 256>>>((const float4*)Wk, (const float4*)Wv);

    // K1: queries
    xq_kernel<<<Ll, Ee>>>(lq, Wq);

    // K2: fp16 K|V projection with fused RoPE epilogue
    gemm_kv_f16<<<dim3(2, MROWS / 128), 256, GEMM16_SMEM>>>(offs, cosT, sinT);

    // K3: tensor-core attention
    attn3<<<dim3(KVHn, BKTOT), 256, ATTN3_SMEM>>>(slen);

    // K4: output projection (tf32)
    gemm_mma<<<dim3(Ee / 128, (BKTOT * Ll) / 128), 256>>>(
        (const float*)att_p, Wo, Wo, 1 << 30, out, Ee, HD);
}

// round 8
// speedup vs baseline: 4.3463x; 1.1339x over previous
#include <cuda_runtime.h>
#include <cuda_fp16.h>
#include <math.h>
#include <math_constants.h>
#include <stdint.h>

// Problem constants
#define Bb   16
#define Kk   16
#define Ss   512
#define Ee   512
#define Ll   16
#define Hh   8
#define KVHn 2
#define Dd   64
#define HD   (Hh*Dd)        // 512
#define KVHD (KVHn*Dd)      // 128
#define NKV  (2*KVHD)       // 256
#define BKTOT (Bb*Kk)       // 256
#define MROWS (BKTOT*Ss)    // 131072

// Scratch (static device globals)
__device__ __half g_wkv_h[NKV * Ee];               // [Wk;Wv] fp16
__device__ __half g_xkv_h[(size_t)MROWS * NKV];    // K(rope'd)|V fp16
__device__ __half g_xq_h[KVHn * 64 * Dd];          // q fp16 [kvh][hh*16+l][d], pre-scaled
__device__ float  g_att[(size_t)BKTOT * Ll * HD];  // attention out fp32

// ---------------------------------------------------------------------------
// PTX helpers
// ---------------------------------------------------------------------------
__device__ __forceinline__ void cp_async16(uint32_t saddr, const void* gptr) {
    asm volatile("cp.async.cg.shared.global [%0], [%1], 16;"
                 :: "r"(saddr), "l"(gptr) : "memory");
}
#define CP_COMMIT() asm volatile("cp.async.commit_group;" ::: "memory")
#define CP_WAIT(n)  asm volatile("cp.async.wait_group %0;" :: "n"(n) : "memory")

__device__ __forceinline__ uint32_t lds32(uint32_t addr) {
    uint32_t v;
    asm volatile("ld.shared.b32 %0, [%1];" : "=r"(v) : "r"(addr));
    return v;
}

__device__ __forceinline__ uint32_t f2tf32(float f) {
    uint32_t r;
    asm("cvt.rna.tf32.f32 %0, %1;" : "=r"(r) : "f"(f));
    return r;
}

__device__ __forceinline__ void mma_tf32(float* c, const uint32_t* a, const uint32_t* b) {
    asm volatile(
        "mma.sync.aligned.m16n8k8.row.col.f32.tf32.tf32.f32 "
        "{%0,%1,%2,%3}, {%4,%5,%6,%7}, {%8,%9}, {%0,%1,%2,%3};"
        : "+f"(c[0]), "+f"(c[1]), "+f"(c[2]), "+f"(c[3])
        : "r"(a[0]), "r"(a[1]), "r"(a[2]), "r"(a[3]), "r"(b[0]), "r"(b[1]));
}

__device__ __forceinline__ void mma_f16(float* c, const uint32_t* a, const uint32_t* b) {
    asm volatile(
        "mma.sync.aligned.m16n8k16.row.col.f32.f16.f16.f32 "
        "{%0,%1,%2,%3}, {%4,%5,%6,%7}, {%8,%9}, {%0,%1,%2,%3};"
        : "+f"(c[0]), "+f"(c[1]), "+f"(c[2]), "+f"(c[3])
        : "r"(a[0]), "r"(a[1]), "r"(a[2]), "r"(a[3]), "r"(b[0]), "r"(b[1]));
}

__device__ __forceinline__ void ldsm_x4(uint32_t* r, uint32_t addr) {
    asm volatile("ldmatrix.sync.aligned.m8n8.x4.shared.b16 {%0,%1,%2,%3}, [%4];"
        : "=r"(r[0]), "=r"(r[1]), "=r"(r[2]), "=r"(r[3]) : "r"(addr));
}
__device__ __forceinline__ void ldsm_x4_t(uint32_t* r, uint32_t addr) {
    asm volatile("ldmatrix.sync.aligned.m8n8.x4.trans.shared.b16 {%0,%1,%2,%3}, [%4];"
        : "=r"(r[0]), "=r"(r[1]), "=r"(r[2]), "=r"(r[3]) : "r"(addr));
}

// ---------------------------------------------------------------------------
// conv_w: Wk|Wv fp32 -> fp16 (tiny)
// ---------------------------------------------------------------------------
__global__ void conv_w(const float4* __restrict__ Wk, const float4* __restrict__ Wv)
{
    int i = blockIdx.x * blockDim.x + threadIdx.x;   // < NKV*Ee/4 = 32768
    const int half1 = KVHD * Ee / 4;
    float4 v = (i < half1) ? Wk[i] : Wv[i - half1];
    __half2* dst = reinterpret_cast<__half2*>(g_wkv_h);
    dst[2 * i]     = __floats2half2_rn(v.x, v.y);
    dst[2 * i + 1] = __floats2half2_rn(v.z, v.w);
}

// ---------------------------------------------------------------------------
// K1: xq = (latent_query @ Wq^T) / sqrt(D), stored fp16 grouped by kvh
// ---------------------------------------------------------------------------
__global__ void xq_kernel(const float* __restrict__ lq, const float* __restrict__ Wq)
{
    int l = blockIdx.x;
    __shared__ float qs[Ee];
    for (int e = threadIdx.x; e < Ee; e += blockDim.x) qs[e] = lq[l * Ee + e];
    __syncthreads();
    int j = threadIdx.x;
    const float* w = Wq + (size_t)j * Ee;
    float acc = 0.f;
#pragma unroll 8
    for (int e = 0; e < Ee; e++) acc += qs[e] * __ldg(&w[e]);
    int h = j >> 6, d = j & 63;
    g_xq_h[((h >> 2) * 64 + (h & 3) * 16 + l) * 64 + d] = __float2half(acc * 0.125f);
}

// ---------------------------------------------------------------------------
// K2: fused fp32->fp16 + GEMM xkv = spike @ [Wk;Wv]^T, RoPE epilogue.
// CTA tile 128m x 256n, 512 threads (16 warps: 4m x 4n), warp tile 32x64.
// A: fp32 spike via cp.async (dbl buf), converted per-iter into fp16 Ah.
// B: fp16 weights via cp.async (triple buf). 16 k-iters of 32.
// smem: A32 2x16384 | B 3x20480 | Ah 10240 = 104448 bytes.
// ---------------------------------------------------------------------------
#define A32OFF 0
#define BOFF   32768
#define AHOFF  94208
#define K2_SMEM 104448

__global__ void __launch_bounds__(512, 1) gemm_kv_f16(
    const float* __restrict__ spike,
    const int* __restrict__ offs,
    const float* __restrict__ cosT,
    const float* __restrict__ sinT)
{
    extern __shared__ char sm_raw[];
    uint32_t sb = (uint32_t)__cvta_generic_to_shared(sm_raw);

    int tid  = threadIdx.x;
    int wid  = tid >> 5, lane = tid & 31;
    int m0   = blockIdx.x * 128;
    int wm   = (wid & 3) * 32;
    int wn   = (wid >> 2) * 64;

    float acc[2][8][4];
#pragma unroll
    for (int mt = 0; mt < 2; mt++)
#pragma unroll
        for (int nt = 0; nt < 8; nt++)
#pragma unroll
            for (int j = 0; j < 4; j++) acc[mt][nt][j] = 0.f;

    // A loader: 1024 chunks of 16B (=4 floats); thread -> chunks tid, tid+512
    int arow0 = tid >> 3,          ach0 = tid & 7;
    int arow1 = (tid + 512) >> 3,  ach1 = (tid + 512) & 7;
    const float* agp0 = spike + (size_t)(m0 + arow0) * Ee + ach0 * 4;
    const float* agp1 = spike + (size_t)(m0 + arow1) * Ee + ach1 * 4;
    uint32_t asd0 = sb + A32OFF + (uint32_t)arow0 * 128 + ach0 * 16;
    uint32_t asd1 = sb + A32OFF + (uint32_t)arow1 * 128 + ach1 * 16;

    // B loader: 1024 chunks of 16B (=8 halves); 256 rows x 4 chunks, stride 80B
    int brow0 = tid >> 2,          bch0 = tid & 3;
    int brow1 = (tid + 512) >> 2,  bch1 = (tid + 512) & 3;
    const __half* bgp0 = g_wkv_h + (size_t)brow0 * Ee + bch0 * 8;
    const __half* bgp1 = g_wkv_h + (size_t)brow1 * Ee + bch1 * 8;
    uint32_t bsd0 = sb + BOFF + (uint32_t)brow0 * 80 + bch0 * 16;
    uint32_t bsd1 = sb + BOFF + (uint32_t)brow1 * 80 + bch1 * 16;

    auto issue = [&](int it) {
        uint32_t ao = (uint32_t)(it & 1) * 16384;
        uint32_t bo = (uint32_t)(it % 3) * 20480;
        int kc = it * 32;
        cp_async16(asd0 + ao, agp0 + kc);
        cp_async16(asd1 + ao, agp1 + kc);
        cp_async16(bsd0 + bo, bgp0 + kc);
        cp_async16(bsd1 + bo, bgp1 + kc);
        CP_COMMIT();
    };

    issue(0);
    issue(1);

    // convert mapping: thread -> 8 floats: row = tid>>2, col group = (tid&3)*8
    int crow = tid >> 2, ccol = (tid & 3) * 8;
    uint32_t csrc = sb + A32OFF + (uint32_t)crow * 128 + ccol * 4;
    uint32_t cdst = sb + AHOFF + (uint32_t)crow * 80 + ccol * 2;
    const float* ahf = (const float*)(sm_raw + AHOFF);   // for type only

    for (int it = 0; it < 16; it++) {
        if (it == 15) CP_WAIT(0); else CP_WAIT(1);
        __syncthreads();

        // convert A32[it&1] -> Ah (fp16)
        {
            uint32_t so = (uint32_t)(it & 1) * 16384;
            float4 v0, v1;
            asm volatile("ld.shared.v4.f32 {%0,%1,%2,%3}, [%4];"
                : "=f"(v0.x), "=f"(v0.y), "=f"(v0.z), "=f"(v0.w) : "r"(csrc + so));
            asm volatile("ld.shared.v4.f32 {%0,%1,%2,%3}, [%4];"
                : "=f"(v1.x), "=f"(v1.y), "=f"(v1.z), "=f"(v1.w) : "r"(csrc + so + 16));
            __half2 h0 = __floats2half2_rn(v0.x, v0.y);
            __half2 h1 = __floats2half2_rn(v0.z, v0.w);
            __half2 h2 = __floats2half2_rn(v1.x, v1.y);
            __half2 h3 = __floats2half2_rn(v1.z, v1.w);
            asm volatile("st.shared.v4.b32 [%0], {%1,%2,%3,%4};"
                :: "r"(cdst),
                   "r"(*(uint32_t*)&h0), "r"(*(uint32_t*)&h1),
                   "r"(*(uint32_t*)&h2), "r"(*(uint32_t*)&h3) : "memory");
        }
        __syncthreads();
        if (it + 2 < 16) issue(it + 2);

        uint32_t Ah = sb + AHOFF;
        uint32_t Bs = sb + BOFF + (uint32_t)(it % 3) * 20480;
#pragma unroll
        for (int ks = 0; ks < 2; ks++) {
            int k0b = (ks * 16 + (lane & 3) * 2) * 2;
            uint32_t af[2][4], bf[8][2];
#pragma unroll
            for (int mt = 0; mt < 2; mt++) {
                uint32_t b0 = Ah + (uint32_t)(wm + mt * 16 + (lane >> 2)) * 80 + k0b;
                af[mt][0] = lds32(b0);
                af[mt][1] = lds32(b0 + 8 * 80);
                af[mt][2] = lds32(b0 + 16);
                af[mt][3] = lds32(b0 + 8 * 80 + 16);
            }
#pragma unroll
            for (int nt = 0; nt < 8; nt++) {
                uint32_t b0 = Bs + (uint32_t)(wn + nt * 8 + (lane >> 2)) * 80 + k0b;
                bf[nt][0] = lds32(b0);
                bf[nt][1] = lds32(b0 + 16);
            }
#pragma unroll
            for (int mt = 0; mt < 2; mt++)
#pragma unroll
                for (int nt = 0; nt < 8; nt++)
                    mma_f16(acc[mt][nt], af[mt], bf[nt]);
        }
    }
    (void)ahf;

    // Epilogue -> fp16 xkv; RoPE on K cols (wn < 128), direct store for V.
    __half2* outp = reinterpret_cast<__half2*>(g_xkv_h);
    if (wn < 128) {
#pragma unroll
        for (int mt = 0; mt < 2; mt++) {
            int r0 = m0 + wm + mt * 16 + (lane >> 2);
            int r1 = r0 + 8;
            int o0 = __ldg(&offs[r0]) * Dd;
            int o1 = __ldg(&offs[r1]) * Dd;
#pragma unroll
            for (int nt = 0; nt < 4; nt++) {
                int dbase = nt * 8 + (lane & 3) * 2;   // local d in [0,32)
                float lo0[2], hi0[2], lo1[2], hi1[2];
#pragma unroll
                for (int j = 0; j < 2; j++) {
                    int d = dbase + j;
                    float c0 = __ldg(&cosT[o0 + d]), s0 = __ldg(&sinT[o0 + d]);
                    float c1 = __ldg(&cosT[o1 + d]), s1 = __ldg(&sinT[o1 + d]);
                    float u = acc[mt][nt][j],     v = acc[mt][nt + 4][j];
                    lo0[j] = u * c0 - v * s0;  hi0[j] = v * c0 + u * s0;
                    u = acc[mt][nt][j + 2];    v = acc[mt][nt + 4][j + 2];
                    lo1[j] = u * c1 - v * s1;  hi1[j] = v * c1 + u * s1;
                }
                int col = wn + dbase;                  // 0..127 even
                outp[((size_t)r0 * NKV + col) >> 1]        = __floats2half2_rn(lo0[0], lo0[1]);
                outp[((size_t)r0 * NKV + col + 32) >> 1]   = __floats2half2_rn(hi0[0], hi0[1]);
                outp[((size_t)r1 * NKV + col) >> 1]        = __floats2half2_rn(lo1[0], lo1[1]);
                outp[((size_t)r1 * NKV + col + 32) >> 1]   = __floats2half2_rn(hi1[0], hi1[1]);
            }
        }
    } else {
#pragma unroll
        for (int mt = 0; mt < 2; mt++) {
            int r0 = m0 + wm + mt * 16 + (lane >> 2);
            int r1 = r0 + 8;
#pragma unroll
            for (int nt = 0; nt < 8; nt++) {
                int col = wn + nt * 8 + (lane & 3) * 2;   // 128..255
                outp[((size_t)r0 * NKV + col) >> 1] =
                    __floats2half2_rn(acc[mt][nt][0], acc[mt][nt][1]);
                outp[((size_t)r1 * NKV + col) >> 1] =
                    __floats2half2_rn(acc[mt][nt][2], acc[mt][nt][3]);
            }
        }
    }
}

// ---------------------------------------------------------------------------
// K3: tensor-core attention (unchanged from R6)
// ---------------------------------------------------------------------------
#define KOFF 0
#define VOFF 73728
#define QOFF 147456
#define ROFF 156672
#define ATTN3_SMEM (ROFF + 1024)

__global__ void __launch_bounds__(256, 1) attn3(const int* __restrict__ slen)
{
    extern __shared__ char sm[];
    uint32_t sb = (uint32_t)__cvta_generic_to_shared(sm);
    int tid = threadIdx.x, lane = tid & 31, wid = tid >> 5;
    int kvh = blockIdx.x, bk = blockIdx.y;
    size_t base = (size_t)bk * Ss;
    int mt = wid & 3, nh = wid >> 2;
    int m0 = mt * 16;

#pragma unroll
    for (int i = 0; i < 16; i++) {
        int cid = tid + i * 256; int row = cid >> 3, ch = cid & 7;
        cp_async16(sb + KOFF + row * 144 + ch * 16,
                   g_xkv_h + (base + row) * NKV + kvh * 64 + ch * 8);
    }
#pragma unroll
    for (int i = 0; i < 2; i++) {
        int cid = tid + i * 256; int row = cid >> 3, ch = cid & 7;
        cp_async16(sb + QOFF + row * 144 + ch * 16,
                   g_xq_h + (kvh * 64 + row) * 64 + ch * 8);
    }
    CP_COMMIT();
#pragma unroll
    for (int i = 0; i < 16; i++) {
        int cid = tid + i * 256; int row = cid >> 3, ch = cid & 7;
        cp_async16(sb + VOFF + row * 144 + ch * 16,
                   g_xkv_h + (base + row) * NKV + 128 + kvh * 64 + ch * 8);
    }
    CP_COMMIT();

    int len = slen[bk];

    CP_WAIT(1);
    __syncthreads();

    float acc[32][4];
#pragma unroll
    for (int nf = 0; nf < 32; nf++)
#pragma unroll
        for (int j = 0; j < 4; j++) acc[nf][j] = 0.f;

    uint32_t aab = sb + QOFF + (uint32_t)(m0 + (lane & 15)) * 144 + (lane >> 4) * 16;
#pragma unroll
    for (int kt = 0; kt < 4; kt++) {
        uint32_t a[4];
        ldsm_x4(a, aab + kt * 32);
#pragma unroll
        for (int np = 0; np < 16; np++) {
            uint32_t b[4];
            ldsm_x4(b, sb + KOFF + (uint32_t)(nh * 256 + np * 16 + (lane & 15)) * 144
                         + kt * 32 + (lane >> 4) * 16);
            uint32_t bp0[2] = {b[0], b[2]}, bp1[2] = {b[1], b[3]};
            mma_f16(acc[2 * np],     a, bp0);
            mma_f16(acc[2 * np + 1], a, bp1);
        }
    }

    int scol = nh * 256 + (lane & 3) * 2;
    float mx0 = -CUDART_INF_F, mx1 = -CUDART_INF_F;
#pragma unroll
    for (int nf = 0; nf < 32; nf++) {
        int s0 = scol + nf * 8;
        if (s0 >= len)     { acc[nf][0] = -CUDART_INF_F; acc[nf][2] = -CUDART_INF_F; }
        if (s0 + 1 >= len) { acc[nf][1] = -CUDART_INF_F; acc[nf][3] = -CUDART_INF_F; }
        mx0 = fmaxf(mx0, fmaxf(acc[nf][0], acc[nf][1]));
        mx1 = fmaxf(mx1, fmaxf(acc[nf][2], acc[nf][3]));
    }
    mx0 = fmaxf(mx0, __shfl_xor_sync(0xffffffffu, mx0, 1));
    mx0 = fmaxf(mx0, __shfl_xor_sync(0xffffffffu, mx0, 2));
    mx1 = fmaxf(mx1, __shfl_xor_sync(0xffffffffu, mx1, 1));
    mx1 = fmaxf(mx1, __shfl_xor_sync(0xffffffffu, mx1, 2));

    float* redm = (float*)(sm + ROFF);
    float* reds = redm + 128;
    int r0 = m0 + (lane >> 2), r1 = r0 + 8;
    if ((lane & 3) == 0) { redm[r0 * 2 + nh] = mx0; redm[r1 * 2 + nh] = mx1; }
    __syncthreads();
    mx0 = fmaxf(redm[r0 * 2], redm[r0 * 2 + 1]);
    mx1 = fmaxf(redm[r1 * 2], redm[r1 * 2 + 1]);

    float sum0 = 0.f, sum1 = 0.f;
#pragma unroll
    for (int nf = 0; nf < 32; nf++) {
        acc[nf][0] = __expf(acc[nf][0] - mx0);
        acc[nf][1] = __expf(acc[nf][1] - mx0);
        acc[nf][2] = __expf(acc[nf][2] - mx1);
        acc[nf][3] = __expf(acc[nf][3] - mx1);
        sum0 += acc[nf][0] + acc[nf][1];
        sum1 += acc[nf][2] + acc[nf][3];
    }
    sum0 += __shfl_xor_sync(0xffffffffu, sum0, 1);
    sum0 += __shfl_xor_sync(0xffffffffu, sum0, 2);
    sum1 += __shfl_xor_sync(0xffffffffu, sum1, 1);
    sum1 += __shfl_xor_sync(0xffffffffu, sum1, 2);
    if ((lane & 3) == 0) { reds[r0 * 2 + nh] = sum0; reds[r1 * 2 + nh] = sum1; }
    __syncthreads();
    float inv0 = 1.f / (reds[r0 * 2] + reds[r0 * 2 + 1]);
    float inv1 = 1.f / (reds[r1 * 2] + reds[r1 * 2 + 1]);

#pragma unroll
    for (int nf = 0; nf < 32; nf++) {
        int s2 = scol + nf * 8;
        *(__half2*)(sm + KOFF + (size_t)r0 * 1040 + s2 * 2) =
            __floats2half2_rn(acc[nf][0], acc[nf][1]);
        *(__half2*)(sm + KOFF + (size_t)r1 * 1040 + s2 * 2) =
            __floats2half2_rn(acc[nf][2], acc[nf][3]);
    }
    CP_WAIT(0);
    __syncthreads();

    float oc[4][4];
#pragma unroll
    for (int i = 0; i < 4; i++)
#pragma unroll
        for (int j = 0; j < 4; j++) oc[i][j] = 0.f;

    uint32_t pab = sb + KOFF + (uint32_t)(m0 + (lane & 15)) * 1040 + (lane >> 4) * 16;
    int dbase = nh * 32;
#pragma unroll 4
    for (int kt = 0; kt < 32; kt++) {
        uint32_t a[4];
        ldsm_x4(a, pab + kt * 32);
        uint32_t vaddr = sb + VOFF + (uint32_t)(kt * 16 + (lane & 15)) * 144
                       + (dbase + (lane >> 4) * 8) * 2;
        uint32_t b[4];
        ldsm_x4_t(b, vaddr);
        {
            uint32_t bp0[2] = {b[0], b[1]}, bp1[2] = {b[2], b[3]};
            mma_f16(oc[0], a, bp0);
            mma_f16(oc[1], a, bp1);
        }
        ldsm_x4_t(b, vaddr + 32);
        {
            uint32_t bp0[2] = {b[0], b[1]}, bp1[2] = {b[2], b[3]};
            mma_f16(oc[2], a, bp0);
            mma_f16(oc[3], a, bp1);
        }
    }

    float* orow0 = g_att + (((size_t)bk * Ll + (r0 & 15)) * Hh + kvh * 4 + (r0 >> 4)) * Dd;
    float* orow1 = g_att + (((size_t)bk * Ll + (r1 & 15)) * Hh + kvh * 4 + (r1 >> 4)) * Dd;
#pragma unroll
    for (int nf = 0; nf < 4; nf++) {
        int d = dbase + nf * 8 + (lane & 3) * 2;
        *(float2*)(orow0 + d) = make_float2(oc[nf][0] * inv0, oc[nf][1] * inv0);
        *(float2*)(orow1 + d) = make_float2(oc[nf][2] * inv1, oc[nf][3] * inv1);
    }
}

// ---------------------------------------------------------------------------
// K4: tf32 NT GEMM for out = att @ Wo^T  (unchanged)
// ---------------------------------------------------------------------------
#define PADW 20

__global__ void __launch_bounds__(256, 2) gemm_mma(
    const float* __restrict__ A,
    const float* __restrict__ B0,
    const float* __restrict__ B1,
    int nsplit,
    float* __restrict__ C,
    int N, int Kd)
{
    __shared__ float As[2][128 * PADW];
    __shared__ float Bs[2][128 * PADW];

    int tid  = threadIdx.x;
    int wid  = tid >> 5, lane = tid & 31;
    int m0   = blockIdx.y * 128;
    int n0   = blockIdx.x * 128;
    int wm   = (wid & 3) * 32;
    int wn   = (wid >> 2) * 64;

    float acc[2][8][4];
#pragma unroll
    for (int mt = 0; mt < 2; mt++)
#pragma unroll
        for (int nt = 0; nt < 8; nt++)
#pragma unroll
            for (int j = 0; j < 4; j++) acc[mt][nt][j] = 0.f;

    int ldrow = tid >> 2;
    int ldc   = (tid & 3) * 4;

    const float* ag0 = A + (size_t)(m0 + ldrow)      * Kd + ldc;
    const float* ag1 = A + (size_t)(m0 + ldrow + 64) * Kd + ldc;
    int nr0 = n0 + ldrow, nr1 = n0 + ldrow + 64;
    const float* bg0 = ((nr0 < nsplit) ? B0 + (size_t)nr0 * Kd
                                       : B1 + (size_t)(nr0 - nsplit) * Kd) + ldc;
    const float* bg1 = ((nr1 < nsplit) ? B0 + (size_t)nr1 * Kd
                                       : B1 + (size_t)(nr1 - nsplit) * Kd) + ldc;

    uint32_t sa_base = (uint32_t)__cvta_generic_to_shared(&As[0][0]);
    uint32_t sb_base = (uint32_t)__cvta_generic_to_shared(&Bs[0][0]);
    uint32_t stg_sz  = 128 * PADW * 4;
    uint32_t dA0 = sa_base + ((uint32_t)ldrow * PADW + ldc) * 4;
    uint32_t dA1 = sa_base + ((uint32_t)(ldrow + 64) * PADW + ldc) * 4;
    uint32_t dB0 = sb_base + ((uint32_t)ldrow * PADW + ldc) * 4;
    uint32_t dB1 = sb_base + ((uint32_t)(ldrow + 64) * PADW + ldc) * 4;

    int NIT = Kd >> 4;

    cp_async16(dA0, ag0); cp_async16(dA1, ag1);
    cp_async16(dB0, bg0); cp_async16(dB1, bg1);
    CP_COMMIT();

    for (int it = 0; it < NIT; it++) {
        int cur = it & 1;
        if (it + 1 < NIT) {
            int nk  = (it + 1) << 4;
            uint32_t so = (uint32_t)((it + 1) & 1) * stg_sz;
            cp_async16(dA0 + so, ag0 + nk); cp_async16(dA1 + so, ag1 + nk);
            cp_async16(dB0 + so, bg0 + nk); cp_async16(dB1 + so, bg1 + nk);
            CP_COMMIT();
            CP_WAIT(1);
        } else {
            CP_WAIT(0);
        }
        __syncthreads();

        const float* as = As[cur];
        const float* bs = Bs[cur];
#pragma unroll
        for (int ks = 0; ks < 2; ks++) {
            int k0 = ks * 8 + (lane & 3);
            uint32_t af[2][4], bf[8][2];
#pragma unroll
            for (int mt = 0; mt < 2; mt++) {
                int r = wm + mt * 16 + (lane >> 2);
                af[mt][0] = f2tf32(as[r * PADW + k0]);
                af[mt][1] = f2tf32(as[(r + 8) * PADW + k0]);
                af[mt][2] = f2tf32(as[r * PADW + k0 + 4]);
                af[mt][3] = f2tf32(as[(r + 8) * PADW + k0 + 4]);
            }
#pragma unroll
            for (int nt = 0; nt < 8; nt++) {
                int n = wn + nt * 8 + (lane >> 2);
                bf[nt][0] = f2tf32(bs[n * PADW + k0]);
                bf[nt][1] = f2tf32(bs[n * PADW + k0 + 4]);
            }
#pragma unroll
            for (int mt = 0; mt < 2; mt++)
#pragma unroll
                for (int nt = 0; nt < 8; nt++)
                    mma_tf32(acc[mt][nt], af[mt], bf[nt]);
        }
        __syncthreads();
    }

#pragma unroll
    for (int mt = 0; mt < 2; mt++) {
        int row = m0 + wm + mt * 16 + (lane >> 2);
#pragma unroll
        for (int nt = 0; nt < 8; nt++) {
            int col = n0 + wn + nt * 8 + (lane & 3) * 2;
            *reinterpret_cast<float2*>(C + (size_t)row * N + col) =
                make_float2(acc[mt][nt][0], acc[mt][nt][1]);
            *reinterpret_cast<float2*>(C + (size_t)(row + 8) * N + col) =
                make_float2(acc[mt][nt][2], acc[mt][nt][3]);
        }
    }
}

// ---------------------------------------------------------------------------
extern "C" void kernel_launch(void* const* d_in, const int* in_sizes, int n_in,
                              void* d_out, int out_size)
{
    const float* spike  = (const float*)d_in[0];
    const int*   offs   = (const int*)  d_in[1];
    const int*   slen   = (const int*)  d_in[2];
    const float* cosT   = (const float*)d_in[3];
    const float* sinT   = (const float*)d_in[4];
    const float* lq     = (const float*)d_in[5];
    const float* Wq     = (const float*)d_in[6];
    const float* Wk     = (const float*)d_in[7];
    const float* Wv     = (const float*)d_in[8];
    const float* Wo     = (const float*)d_in[9];
    float* out = (float*)d_out;

    void* att_p = nullptr;
    cudaGetSymbolAddress(&att_p, g_att);

    cudaFuncSetAttribute(gemm_kv_f16,
                         cudaFuncAttributeMaxDynamicSharedMemorySize, K2_SMEM);
    cudaFuncSetAttribute(attn3,
                         cudaFuncAttributeMaxDynamicSharedMemorySize, ATTN3_SMEM);

    // Weights fp16 + queries
    conv_w<<<128, 256>>>((const float4*)Wk, (const float4*)Wv);
    xq_kernel<<<Ll, Ee>>>(lq, Wq);

    // K2: fused convert + fp16 K|V projection with RoPE epilogue
    gemm_kv_f16<<<MROWS / 128, 512, K2_SMEM>>>(spike, offs, cosT, sinT);

    // K3: tensor-core attention
    attn3<<<dim3(KVHn, BKTOT), 256, ATTN3_SMEM>>>(slen);

    // K4: output projection (tf32)
    gemm_mma<<<dim3(Ee / 128, (BKTOT * Ll) / 128), 256>>>(
        (const float*)att_p, Wo, Wo, 1 << 30, out, Ee, HD);
}